// round 7
// baseline (speedup 1.0000x reference)
#include <cuda_runtime.h>
#include <cuda_bf16.h>
#include <math.h>
#include <stdint.h>

#define BSZ 8192
#define KN  32
#define DD  512
#define NCHUNK 4
#define CH_ROWS (BSZ / NCHUNK)

// ---------------------------------------------------------------------------
// Device scratch
// ---------------------------------------------------------------------------
__device__ __nv_bfloat16 g_Mth[DD * DD];   // bf16 hi of Mt[d][j] = sum_e w1[e][j] w2[e][d]
__device__ __nv_bfloat16 g_Mtl[DD * DD];   // bf16 lo
__device__ float g_q2[BSZ * DD];           // x @ M + c
__device__ float g_c[DD];                  // b1 @ w2
__device__ float g_u[DD];                  // b2 @ w1
__device__ float g_s0;                     // b1 . b2

// ---------------------------------------------------------------------------
// Helpers
// ---------------------------------------------------------------------------
__device__ __forceinline__ uint32_t smem_u32(const void* p) {
    uint32_t a;
    asm("{ .reg .u64 t; cvta.to.shared.u64 t, %1; cvt.u32.u64 %0, t; }"
        : "=r"(a) : "l"(p));
    return a;
}
__device__ __forceinline__ void cp16(uint32_t saddr, const void* g) {
    asm volatile("cp.async.cg.shared.global [%0], [%1], 16;"
                 :: "r"(saddr), "l"(g));
}
__device__ __forceinline__ void ldsm4(uint32_t* r, uint32_t addr) {
    asm volatile("ldmatrix.sync.aligned.m8n8.x4.shared.b16 {%0,%1,%2,%3}, [%4];"
                 : "=r"(r[0]), "=r"(r[1]), "=r"(r[2]), "=r"(r[3]) : "r"(addr));
}
__device__ __forceinline__ void mma16816(float* c, const uint32_t* a,
                                         uint32_t b0, uint32_t b1) {
    asm volatile(
        "mma.sync.aligned.m16n8k16.row.col.f32.bf16.bf16.f32 "
        "{%0,%1,%2,%3}, {%4,%5,%6,%7}, {%8,%9}, {%0,%1,%2,%3};"
        : "+f"(c[0]), "+f"(c[1]), "+f"(c[2]), "+f"(c[3])
        : "r"(a[0]), "r"(a[1]), "r"(a[2]), "r"(a[3]), "r"(b0), "r"(b1));
}

// ---------------------------------------------------------------------------
// precompute_all: cp.async double-buffered register-tiled fp32 GEMM.
//   Mt[d][j] = sum_e w1[e][j] * w2[e][d]  -> bf16 hi/lo split store
//   u[j] (by==0), c[d] (bx==0), s0 (block 0,0) fused.
// Grid (8, 8), 256 threads, 64x64 tile, 4x4 per thread.
// ---------------------------------------------------------------------------
__global__ __launch_bounds__(256) void precompute_all(
    const float* __restrict__ w1, const float* __restrict__ w2,
    const float* __restrict__ b1, const float* __restrict__ b2) {
    __shared__ float s1[2][32][64];
    __shared__ float s2[2][32][64];
    __shared__ float sb1[DD], sb2[DD];
    int tid = threadIdx.x;
    int tc = tid & 15;
    int tr = tid >> 4;
    int j0 = blockIdx.x * 64, d0 = blockIdx.y * 64;

    sb1[tid] = b1[tid]; sb1[tid + 256] = b1[tid + 256];
    sb2[tid] = b2[tid]; sb2[tid + 256] = b2[tid + 256];

    uint32_t s1b = smem_u32(&s1[0][0][0]);
    uint32_t s2b = smem_u32(&s2[0][0][0]);

    auto load_tile = [&](int st, int e0) {
        int row = tid >> 4, q = tid & 15;
#pragma unroll
        for (int i = 0; i < 2; i++) {
            int r = row + 16 * i;
            cp16(s1b + (uint32_t)((st * 32 + r) * 64 + q * 4) * 4,
                 w1 + (size_t)(e0 + r) * DD + j0 + q * 4);
            cp16(s2b + (uint32_t)((st * 32 + r) * 64 + q * 4) * 4,
                 w2 + (size_t)(e0 + r) * DD + d0 + q * 4);
        }
        asm volatile("cp.async.commit_group;" ::: "memory");
    };

    float acc[4][4];
#pragma unroll
    for (int r = 0; r < 4; r++)
#pragma unroll
        for (int c = 0; c < 4; c++) acc[r][c] = 0.f;
    float uacc = 0.f, cacc = 0.f;

    load_tile(0, 0);

#pragma unroll 1
    for (int t = 0; t < 16; t++) {
        int st = t & 1;
        if (t + 1 < 16) {
            load_tile(st ^ 1, (t + 1) * 32);
            asm volatile("cp.async.wait_group 1;" ::: "memory");
        } else {
            asm volatile("cp.async.wait_group 0;" ::: "memory");
        }
        __syncthreads();
#pragma unroll
        for (int e = 0; e < 32; e++) {
            float4 bv = *(const float4*)&s1[st][e][tc * 4];
            float4 av = *(const float4*)&s2[st][e][tr * 4];
            float br[4] = {bv.x, bv.y, bv.z, bv.w};
            float ar[4] = {av.x, av.y, av.z, av.w};
#pragma unroll
            for (int r = 0; r < 4; r++)
#pragma unroll
                for (int c = 0; c < 4; c++) acc[r][c] += ar[r] * br[c];
        }
        if (blockIdx.y == 0 && tid < 64) {
            int e0 = t * 32;
#pragma unroll
            for (int e = 0; e < 32; e++) uacc += sb2[e0 + e] * s1[st][e][tid];
        }
        if (blockIdx.x == 0 && tid >= 64 && tid < 128) {
            int e0 = t * 32;
#pragma unroll
            for (int e = 0; e < 32; e++) cacc += sb1[e0 + e] * s2[st][e][tid - 64];
        }
        __syncthreads();
    }

#pragma unroll
    for (int r = 0; r < 4; r++) {
        int d = d0 + tr * 4 + r;
        __nv_bfloat16 hv[4], lv[4];
#pragma unroll
        for (int c = 0; c < 4; c++) {
            hv[c] = __float2bfloat16(acc[r][c]);
            lv[c] = __float2bfloat16(acc[r][c] - __bfloat162float(hv[c]));
        }
        *(uint2*)&g_Mth[(size_t)d * DD + j0 + tc * 4] = *(uint2*)hv;
        *(uint2*)&g_Mtl[(size_t)d * DD + j0 + tc * 4] = *(uint2*)lv;
    }
    if (blockIdx.y == 0 && tid < 64) g_u[j0 + tid] = uacc;
    if (blockIdx.x == 0 && tid >= 64 && tid < 128) g_c[d0 + tid - 64] = cacc;
    if (blockIdx.x == 0 && blockIdx.y == 0 && tid < 32) {
        float v = 0.f;
#pragma unroll
        for (int q = 0; q < 16; q++) v += sb1[tid + 32 * q] * sb2[tid + 32 * q];
#pragma unroll
        for (int o = 16; o > 0; o >>= 1) v += __shfl_xor_sync(0xFFFFFFFFu, v, o);
        if (tid == 0) g_s0 = v;
    }
}

// ---------------------------------------------------------------------------
// Fused-split bf16x3 GEMM: q2 = x @ M + c, chunked by m0 (2048 rows/chunk).
// Block tile 128x256, 8 warps (2m x 4n), warp tile 64x64, 80B-padded rows.
// ---------------------------------------------------------------------------
#define NKT 16
#define XH_OFF 0
#define XL_OFF 10240
#define MH_OFF 20480
#define ML_OFF 40960
#define STAGE_STRIDE 61440
#define GSMEM_TOTAL (2 * STAGE_STRIDE + 1024)

__global__ __launch_bounds__(256) void gemm_fused(
    const float* __restrict__ x,
    const __nv_bfloat16* __restrict__ Mth, const __nv_bfloat16* __restrict__ Mtl,
    float* __restrict__ outf, int m0) {
    extern __shared__ char smem[];
    uint32_t sbase = smem_u32(smem);
    int tid = threadIdx.x;
    int lane = tid & 31;
    int warp = tid >> 5;
    int wm = warp >> 2;
    int wn = warp & 3;
    int bx = blockIdx.x;
    int row0 = m0 + blockIdx.y * 128;

    float* sb = (float*)(smem + 2 * STAGE_STRIDE);
    sb[tid] = g_c[bx * 256 + tid];

    float acc[4][8][4];
#pragma unroll
    for (int i = 0; i < 4; i++)
#pragma unroll
        for (int n = 0; n < 8; n++)
#pragma unroll
            for (int q = 0; q < 4; q++) acc[i][n][q] = 0.f;

    int arow  = lane & 15;
    int acol8 = (lane >> 4) * 8;
    int brow  = (lane & 7) + ((lane >> 4) << 3);
    int bcol8 = ((lane >> 3) & 1) * 8;

    auto load_M = [&](int stage, int kt) {
        int kk = kt * 32;
        uint32_t mh = sbase + stage * STAGE_STRIDE + MH_OFF;
        uint32_t ml = sbase + stage * STAGE_STRIDE + ML_OFF;
#pragma unroll
        for (int i = 0; i < 4; i++) {
            int c = tid + 256 * i;
            int n = c >> 2, q = c & 3;
            cp16(mh + n * 80 + q * 16,
                 Mth + (size_t)(bx * 256 + n) * DD + kk + q * 8);
            cp16(ml + n * 80 + q * 16,
                 Mtl + (size_t)(bx * 256 + n) * DD + kk + q * 8);
        }
        asm volatile("cp.async.commit_group;" ::: "memory");
    };

    auto load_x_regs = [&](int kt, float4* vr) {
        int kk = kt * 32;
#pragma unroll
        for (int i = 0; i < 2; i++) {
            int c = tid + 256 * i;
            int r = c >> 2, q = c & 3;
            vr[i] = *(const float4*)(x + (size_t)(row0 + r) * DD + kk + q * 8);
            vr[i + 2] = *(const float4*)(x + (size_t)(row0 + r) * DD + kk + q * 8 + 4);
        }
    };

    auto store_x = [&](int stage, const float4* vr) {
        uint32_t xh = stage * STAGE_STRIDE + XH_OFF;
        uint32_t xl = stage * STAGE_STRIDE + XL_OFF;
#pragma unroll
        for (int i = 0; i < 2; i++) {
            int c = tid + 256 * i;
            int r = c >> 2, q = c & 3;
            float4 v0 = vr[i], v1 = vr[i + 2];
            __nv_bfloat162 h01 = __floats2bfloat162_rn(v0.x, v0.y);
            __nv_bfloat162 h23 = __floats2bfloat162_rn(v0.z, v0.w);
            __nv_bfloat162 h45 = __floats2bfloat162_rn(v1.x, v1.y);
            __nv_bfloat162 h67 = __floats2bfloat162_rn(v1.z, v1.w);
            __nv_bfloat162 l01 = __floats2bfloat162_rn(v0.x - __bfloat162float(h01.x),
                                                       v0.y - __bfloat162float(h01.y));
            __nv_bfloat162 l23 = __floats2bfloat162_rn(v0.z - __bfloat162float(h23.x),
                                                       v0.w - __bfloat162float(h23.y));
            __nv_bfloat162 l45 = __floats2bfloat162_rn(v1.x - __bfloat162float(h45.x),
                                                       v1.y - __bfloat162float(h45.y));
            __nv_bfloat162 l67 = __floats2bfloat162_rn(v1.z - __bfloat162float(h67.x),
                                                       v1.w - __bfloat162float(h67.y));
            union { __nv_bfloat162 b[4]; uint4 u; } ph, pl;
            ph.b[0] = h01; ph.b[1] = h23; ph.b[2] = h45; ph.b[3] = h67;
            pl.b[0] = l01; pl.b[1] = l23; pl.b[2] = l45; pl.b[3] = l67;
            *(uint4*)(smem + xh + r * 80 + q * 16) = ph.u;
            *(uint4*)(smem + xl + r * 80 + q * 16) = pl.u;
        }
    };

    float4 xcur[4];
    load_x_regs(0, xcur);
    load_M(0, 0);
    store_x(0, xcur);

#pragma unroll 1
    for (int kt = 0; kt < NKT; kt++) {
        int cur = kt & 1;
        float4 xnext[4];
        if (kt + 1 < NKT) {
            load_x_regs(kt + 1, xnext);
            load_M(cur ^ 1, kt + 1);
            asm volatile("cp.async.wait_group 1;" ::: "memory");
        } else {
            asm volatile("cp.async.wait_group 0;" ::: "memory");
        }
        __syncthreads();

        uint32_t base = sbase + cur * STAGE_STRIDE;
#pragma unroll
        for (int h = 0; h < 2; h++) {
            uint32_t afh[4][4], afl[4][4];
#pragma unroll
            for (int i = 0; i < 4; i++) {
                uint32_t rowoff = (uint32_t)(wm * 64 + i * 16 + arow) * 80 +
                                  (uint32_t)(h * 16 + acol8) * 2;
                ldsm4(afh[i], base + XH_OFF + rowoff);
                ldsm4(afl[i], base + XL_OFF + rowoff);
            }
            uint32_t bfh[4][4], bfl[4][4];
#pragma unroll
            for (int j = 0; j < 4; j++) {
                uint32_t rowoff = (uint32_t)(wn * 64 + j * 16 + brow) * 80 +
                                  (uint32_t)(h * 16 + bcol8) * 2;
                ldsm4(bfh[j], base + MH_OFF + rowoff);
                ldsm4(bfl[j], base + ML_OFF + rowoff);
            }
#pragma unroll
            for (int i = 0; i < 4; i++)
#pragma unroll
                for (int j = 0; j < 4; j++) {
                    mma16816(acc[i][2 * j],     afh[i], bfh[j][0], bfh[j][1]);
                    mma16816(acc[i][2 * j + 1], afh[i], bfh[j][2], bfh[j][3]);
                    mma16816(acc[i][2 * j],     afh[i], bfl[j][0], bfl[j][1]);
                    mma16816(acc[i][2 * j + 1], afh[i], bfl[j][2], bfl[j][3]);
                    mma16816(acc[i][2 * j],     afl[i], bfh[j][0], bfh[j][1]);
                    mma16816(acc[i][2 * j + 1], afl[i], bfh[j][2], bfh[j][3]);
                }
        }
        if (kt + 1 < NKT) store_x(cur ^ 1, xnext);
        __syncthreads();
    }

    int g = lane >> 2, t4 = lane & 3;
#pragma unroll
    for (int i = 0; i < 4; i++) {
        int r0 = row0 + wm * 64 + i * 16 + g;
#pragma unroll
        for (int n = 0; n < 8; n++) {
            int coll = wn * 64 + n * 8 + 2 * t4;
            int colg = bx * 256 + coll;
            float bx0 = sb[coll], bx1 = sb[coll + 1];
            float2 v0 = make_float2(acc[i][n][0] + bx0, acc[i][n][1] + bx1);
            float2 v1 = make_float2(acc[i][n][2] + bx0, acc[i][n][3] + bx1);
            *(float2*)(outf + (size_t)r0 * DD + colg) = v0;
            *(float2*)(outf + (size_t)(r0 + 8) * DD + colg) = v1;
        }
    }
}

// ---------------------------------------------------------------------------
// Attend, chunked by b0: one warp per row, streams keys+values once.
// ---------------------------------------------------------------------------
__global__ __launch_bounds__(256) void attend(const float* __restrict__ x,
                                              const float* __restrict__ keys,
                                              const float* __restrict__ values,
                                              float* __restrict__ out, int b0) {
    int warp = b0 + ((blockIdx.x * blockDim.x + threadIdx.x) >> 5);
    int lane = threadIdx.x & 31;
    if (warp >= BSZ) return;

    const float4* xr  = (const float4*)(x + (size_t)warp * DD);
    const float4* q2r = (const float4*)(g_q2 + (size_t)warp * DD);
    const float4* kb  = (const float4*)(keys + (size_t)warp * KN * DD);
    const float4* vb  = (const float4*)(values + (size_t)warp * KN * DD);
    const float4* ur  = (const float4*)g_u;

    float4 xv[4], qv[4];
#pragma unroll
    for (int i = 0; i < 4; i++) {
        xv[i] = xr[lane + 32 * i];
        qv[i] = q2r[lane + 32 * i];
    }

    float qb = 0.f;
#pragma unroll
    for (int i = 0; i < 4; i++) {
        float4 uv = ur[lane + 32 * i];
        qb += xv[i].x * uv.x + xv[i].y * uv.y + xv[i].z * uv.z + xv[i].w * uv.w;
    }
#pragma unroll
    for (int o = 16; o > 0; o >>= 1) qb += __shfl_xor_sync(0xFFFFFFFFu, qb, o);
    qb += g_s0;

    const float scale = 0.044194173824159216f;  // 1/sqrt(512)

    float myscore = 0.f;
    float4 cur[4];
#pragma unroll
    for (int i = 0; i < 4; i++) cur[i] = kb[lane + 32 * i];

#pragma unroll
    for (int k = 0; k < KN; k++) {
        float4 nxt[4];
        if (k + 1 < KN) {
#pragma unroll
            for (int i = 0; i < 4; i++) nxt[i] = kb[(k + 1) * 128 + lane + 32 * i];
        }
        float p = 0.f;
#pragma unroll
        for (int i = 0; i < 4; i++) {
            p += qv[i].x * cur[i].x + qv[i].y * cur[i].y +
                 qv[i].z * cur[i].z + qv[i].w * cur[i].w;
        }
#pragma unroll
        for (int o = 16; o > 0; o >>= 1) p += __shfl_xor_sync(0xFFFFFFFFu, p, o);
        float s = (p + qb) * scale;
        if (lane == k) myscore = s;
#pragma unroll
        for (int i = 0; i < 4; i++) cur[i] = nxt[i];
    }

    float m = myscore;
#pragma unroll
    for (int o = 16; o > 0; o >>= 1)
        m = fmaxf(m, __shfl_xor_sync(0xFFFFFFFFu, m, o));
    float e = expf(myscore - m);
    float sum = e;
#pragma unroll
    for (int o = 16; o > 0; o >>= 1) sum += __shfl_xor_sync(0xFFFFFFFFu, sum, o);
    float a = e / sum;

    float4 acc[4];
#pragma unroll
    for (int i = 0; i < 4; i++) acc[i] = make_float4(0.f, 0.f, 0.f, 0.f);

#pragma unroll
    for (int k = 0; k < KN; k++) {
        float w = __shfl_sync(0xFFFFFFFFu, a, k);
#pragma unroll
        for (int i = 0; i < 4; i++) {
            float4 vv = vb[k * 128 + lane + 32 * i];
            acc[i].x += w * vv.x;
            acc[i].y += w * vv.y;
            acc[i].z += w * vv.z;
            acc[i].w += w * vv.w;
        }
    }

    float4* outr = (float4*)(out + (size_t)warp * DD);
#pragma unroll
    for (int i = 0; i < 4; i++) {
        float4 o;
        o.x = 0.5f * xv[i].x + 0.5f * acc[i].x;
        o.y = 0.5f * xv[i].y + 0.5f * acc[i].y;
        o.z = 0.5f * xv[i].z + 0.5f * acc[i].z;
        o.w = 0.5f * xv[i].w + 0.5f * acc[i].w;
        outr[lane + 32 * i] = o;
    }
}

// ---------------------------------------------------------------------------
extern "C" void kernel_launch(void* const* d_in, const int* in_sizes, int n_in,
                              void* d_out, int out_size) {
    const float* x      = (const float*)d_in[0];
    const float* keys   = (const float*)d_in[1];
    const float* values = (const float*)d_in[2];
    const float* w1     = (const float*)d_in[3];
    const float* b1     = (const float*)d_in[4];
    const float* w2     = (const float*)d_in[5];
    const float* b2     = (const float*)d_in[6];
    float* out = (float*)d_out;

    static bool inited = false;
    static cudaStream_t s2;
    static cudaEvent_t evG[NCHUNK], evJ;
    if (!inited) {
        cudaStreamCreateWithFlags(&s2, cudaStreamNonBlocking);
        for (int i = 0; i < NCHUNK; i++)
            cudaEventCreateWithFlags(&evG[i], cudaEventDisableTiming);
        cudaEventCreateWithFlags(&evJ, cudaEventDisableTiming);
        cudaFuncSetAttribute(gemm_fused,
                             cudaFuncAttributeMaxDynamicSharedMemorySize,
                             GSMEM_TOTAL);
        inited = true;
    }

    __nv_bfloat16 *Mth, *Mtl;
    float *q2;
    cudaGetSymbolAddress((void**)&Mth, g_Mth);
    cudaGetSymbolAddress((void**)&Mtl, g_Mtl);
    cudaGetSymbolAddress((void**)&q2, g_q2);

    // main (capture) stream: precompute + gemm chunks
    precompute_all<<<dim3(8, 8), 256>>>(w1, w2, b1, b2);
    for (int i = 0; i < NCHUNK; i++) {
        gemm_fused<<<dim3(2, CH_ROWS / 128), 256, GSMEM_TOTAL>>>(
            x, Mth, Mtl, q2, i * CH_ROWS);
        cudaEventRecord(evG[i], 0);
        cudaStreamWaitEvent(s2, evG[i], 0);
        attend<<<CH_ROWS * 32 / 256, 256, 0, s2>>>(x, keys, values, out,
                                                   i * CH_ROWS);
    }
    cudaEventRecord(evJ, s2);
    cudaStreamWaitEvent(0, evJ, 0);
}

// round 8
// speedup vs baseline: 1.5140x; 1.5140x over previous
#include <cuda_runtime.h>
#include <cuda_bf16.h>
#include <math.h>
#include <stdint.h>

#define BSZ 8192
#define KN  32
#define DD  512

// ---------------------------------------------------------------------------
// Device scratch
// ---------------------------------------------------------------------------
__device__ __nv_bfloat16 g_Mth[DD * DD];   // bf16 hi of Mt[d][j] = sum_e w1[e][j] w2[e][d]
__device__ __nv_bfloat16 g_Mtl[DD * DD];   // bf16 lo
__device__ float g_q2[BSZ * DD];           // x @ M + c
__device__ float g_c[DD];                  // b1 @ w2
__device__ float g_u[DD];                  // b2 @ w1
__device__ float g_s0;                     // b1 . b2

// ---------------------------------------------------------------------------
// Helpers
// ---------------------------------------------------------------------------
__device__ __forceinline__ uint32_t smem_u32(const void* p) {
    uint32_t a;
    asm("{ .reg .u64 t; cvta.to.shared.u64 t, %1; cvt.u32.u64 %0, t; }"
        : "=r"(a) : "l"(p));
    return a;
}
__device__ __forceinline__ void cp16(uint32_t saddr, const void* g) {
    asm volatile("cp.async.cg.shared.global [%0], [%1], 16;"
                 :: "r"(saddr), "l"(g));
}
__device__ __forceinline__ void ldsm4(uint32_t* r, uint32_t addr) {
    asm volatile("ldmatrix.sync.aligned.m8n8.x4.shared.b16 {%0,%1,%2,%3}, [%4];"
                 : "=r"(r[0]), "=r"(r[1]), "=r"(r[2]), "=r"(r[3]) : "r"(addr));
}
__device__ __forceinline__ void mma16816(float* c, const uint32_t* a,
                                         uint32_t b0, uint32_t b1) {
    asm volatile(
        "mma.sync.aligned.m16n8k16.row.col.f32.bf16.bf16.f32 "
        "{%0,%1,%2,%3}, {%4,%5,%6,%7}, {%8,%9}, {%0,%1,%2,%3};"
        : "+f"(c[0]), "+f"(c[1]), "+f"(c[2]), "+f"(c[3])
        : "r"(a[0]), "r"(a[1]), "r"(a[2]), "r"(a[3]), "r"(b0), "r"(b1));
}

// ---------------------------------------------------------------------------
// precompute_all: cp.async double-buffered register-tiled fp32 GEMM.
//   Mt[d][j] = sum_e w1[e][j] * w2[e][d]  -> bf16 hi/lo split store
//   u[j] (by==0), c[d] (bx==0), s0 (block 0,0) fused.
// Grid (8, 8), 256 threads, 64x64 tile, 4x4 per thread.
// ---------------------------------------------------------------------------
__global__ __launch_bounds__(256) void precompute_all(
    const float* __restrict__ w1, const float* __restrict__ w2,
    const float* __restrict__ b1, const float* __restrict__ b2) {
    __shared__ float s1[2][32][64];
    __shared__ float s2[2][32][64];
    __shared__ float sb1[DD], sb2[DD];
    int tid = threadIdx.x;
    int tc = tid & 15;
    int tr = tid >> 4;
    int j0 = blockIdx.x * 64, d0 = blockIdx.y * 64;

    sb1[tid] = b1[tid]; sb1[tid + 256] = b1[tid + 256];
    sb2[tid] = b2[tid]; sb2[tid + 256] = b2[tid + 256];

    uint32_t s1b = smem_u32(&s1[0][0][0]);
    uint32_t s2b = smem_u32(&s2[0][0][0]);

    auto load_tile = [&](int st, int e0) {
        int row = tid >> 4, q = tid & 15;
#pragma unroll
        for (int i = 0; i < 2; i++) {
            int r = row + 16 * i;
            cp16(s1b + (uint32_t)((st * 32 + r) * 64 + q * 4) * 4,
                 w1 + (size_t)(e0 + r) * DD + j0 + q * 4);
            cp16(s2b + (uint32_t)((st * 32 + r) * 64 + q * 4) * 4,
                 w2 + (size_t)(e0 + r) * DD + d0 + q * 4);
        }
        asm volatile("cp.async.commit_group;" ::: "memory");
    };

    float acc[4][4];
#pragma unroll
    for (int r = 0; r < 4; r++)
#pragma unroll
        for (int c = 0; c < 4; c++) acc[r][c] = 0.f;
    float uacc = 0.f, cacc = 0.f;

    load_tile(0, 0);

#pragma unroll 1
    for (int t = 0; t < 16; t++) {
        int st = t & 1;
        if (t + 1 < 16) {
            load_tile(st ^ 1, (t + 1) * 32);
            asm volatile("cp.async.wait_group 1;" ::: "memory");
        } else {
            asm volatile("cp.async.wait_group 0;" ::: "memory");
        }
        __syncthreads();
#pragma unroll
        for (int e = 0; e < 32; e++) {
            float4 bv = *(const float4*)&s1[st][e][tc * 4];
            float4 av = *(const float4*)&s2[st][e][tr * 4];
            float br[4] = {bv.x, bv.y, bv.z, bv.w};
            float ar[4] = {av.x, av.y, av.z, av.w};
#pragma unroll
            for (int r = 0; r < 4; r++)
#pragma unroll
                for (int c = 0; c < 4; c++) acc[r][c] += ar[r] * br[c];
        }
        if (blockIdx.y == 0 && tid < 64) {
            int e0 = t * 32;
#pragma unroll
            for (int e = 0; e < 32; e++) uacc += sb2[e0 + e] * s1[st][e][tid];
        }
        if (blockIdx.x == 0 && tid >= 64 && tid < 128) {
            int e0 = t * 32;
#pragma unroll
            for (int e = 0; e < 32; e++) cacc += sb1[e0 + e] * s2[st][e][tid - 64];
        }
        __syncthreads();
    }

#pragma unroll
    for (int r = 0; r < 4; r++) {
        int d = d0 + tr * 4 + r;
        __nv_bfloat16 hv[4], lv[4];
#pragma unroll
        for (int c = 0; c < 4; c++) {
            hv[c] = __float2bfloat16(acc[r][c]);
            lv[c] = __float2bfloat16(acc[r][c] - __bfloat162float(hv[c]));
        }
        *(uint2*)&g_Mth[(size_t)d * DD + j0 + tc * 4] = *(uint2*)hv;
        *(uint2*)&g_Mtl[(size_t)d * DD + j0 + tc * 4] = *(uint2*)lv;
    }
    if (blockIdx.y == 0 && tid < 64) g_u[j0 + tid] = uacc;
    if (blockIdx.x == 0 && tid >= 64 && tid < 128) g_c[d0 + tid - 64] = cacc;
    if (blockIdx.x == 0 && blockIdx.y == 0 && tid < 32) {
        float v = 0.f;
#pragma unroll
        for (int q = 0; q < 16; q++) v += sb1[tid + 32 * q] * sb2[tid + 32 * q];
#pragma unroll
        for (int o = 16; o > 0; o >>= 1) v += __shfl_xor_sync(0xFFFFFFFFu, v, o);
        if (tid == 0) g_s0 = v;
    }
}

// ---------------------------------------------------------------------------
// Fused-split bf16x3 GEMM: q2 = x @ M + c over physical K=512 (16 k32 tiles).
// Block tile 64x256, 8 warps (2m x 4n), warp tile 32x64, 80B-padded rows.
// Grid (2, 128) = 256 blocks; __launch_bounds__(256,2) caps regs at 128 so
// TWO blocks co-reside per SM (smem 101KB x 2 = 202KB < 228KB carveout).
// ---------------------------------------------------------------------------
#define NKT 16
#define XH_OFF 0
#define XL_OFF 5120
#define MH_OFF 10240
#define ML_OFF 30720
#define STAGE_STRIDE 51200
#define GSMEM_TOTAL (2 * STAGE_STRIDE + 1024)

__global__ __launch_bounds__(256, 2) void gemm_fused(
    const float* __restrict__ x,
    const __nv_bfloat16* __restrict__ Mth, const __nv_bfloat16* __restrict__ Mtl,
    float* __restrict__ outf) {
    extern __shared__ char smem[];
    uint32_t sbase = smem_u32(smem);
    int tid = threadIdx.x;
    int lane = tid & 31;
    int warp = tid >> 5;
    int wm = warp >> 2;            // 0..1 (32-row warp tiles)
    int wn = warp & 3;             // 0..3 (64-col warp tiles)
    int bx = blockIdx.x, by = blockIdx.y;

    float* sb = (float*)(smem + 2 * STAGE_STRIDE);
    sb[tid] = g_c[bx * 256 + tid];

    float acc[2][8][4];
#pragma unroll
    for (int i = 0; i < 2; i++)
#pragma unroll
        for (int n = 0; n < 8; n++)
#pragma unroll
            for (int q = 0; q < 4; q++) acc[i][n][q] = 0.f;

    int arow  = lane & 15;
    int acol8 = (lane >> 4) * 8;
    int brow  = (lane & 7) + ((lane >> 4) << 3);
    int bcol8 = ((lane >> 3) & 1) * 8;

    auto load_M = [&](int stage, int kt) {
        int kk = kt * 32;
        uint32_t mh = sbase + stage * STAGE_STRIDE + MH_OFF;
        uint32_t ml = sbase + stage * STAGE_STRIDE + ML_OFF;
#pragma unroll
        for (int i = 0; i < 4; i++) {
            int c = tid + 256 * i;
            int n = c >> 2, q = c & 3;
            cp16(mh + n * 80 + q * 16,
                 Mth + (size_t)(bx * 256 + n) * DD + kk + q * 8);
            cp16(ml + n * 80 + q * 16,
                 Mtl + (size_t)(bx * 256 + n) * DD + kk + q * 8);
        }
        asm volatile("cp.async.commit_group;" ::: "memory");
    };

    auto load_x_regs = [&](int kt, float4* vr) {
        int kk = kt * 32;
#pragma unroll
        for (int i = 0; i < 2; i++) {
            int c = tid + 256 * i;
            int r = c >> 3, q = c & 7;
            vr[i] = *(const float4*)(x + (size_t)(by * 64 + r) * DD + kk + q * 4);
        }
    };

    auto store_x = [&](int stage, const float4* vr) {
        uint32_t xh = stage * STAGE_STRIDE + XH_OFF;
        uint32_t xl = stage * STAGE_STRIDE + XL_OFF;
#pragma unroll
        for (int i = 0; i < 2; i++) {
            int c = tid + 256 * i;
            int r = c >> 3, q = c & 7;
            float4 v = vr[i];
            __nv_bfloat162 h01 = __floats2bfloat162_rn(v.x, v.y);
            __nv_bfloat162 h23 = __floats2bfloat162_rn(v.z, v.w);
            __nv_bfloat162 l01 = __floats2bfloat162_rn(v.x - __bfloat162float(h01.x),
                                                       v.y - __bfloat162float(h01.y));
            __nv_bfloat162 l23 = __floats2bfloat162_rn(v.z - __bfloat162float(h23.x),
                                                       v.w - __bfloat162float(h23.y));
            union { __nv_bfloat162 b[2]; uint2 u; } ph, pl;
            ph.b[0] = h01; ph.b[1] = h23;
            pl.b[0] = l01; pl.b[1] = l23;
            *(uint2*)(smem + xh + r * 80 + q * 8) = ph.u;
            *(uint2*)(smem + xl + r * 80 + q * 8) = pl.u;
        }
    };

    float4 xcur[2];
    load_x_regs(0, xcur);
    load_M(0, 0);
    store_x(0, xcur);

#pragma unroll 1
    for (int kt = 0; kt < NKT; kt++) {
        int cur = kt & 1;
        float4 xnext[2];
        if (kt + 1 < NKT) {
            load_x_regs(kt + 1, xnext);
            load_M(cur ^ 1, kt + 1);
            asm volatile("cp.async.wait_group 1;" ::: "memory");
        } else {
            asm volatile("cp.async.wait_group 0;" ::: "memory");
        }
        __syncthreads();

        uint32_t base = sbase + cur * STAGE_STRIDE;
#pragma unroll
        for (int h = 0; h < 2; h++) {
            uint32_t afh[2][4], afl[2][4];
#pragma unroll
            for (int i = 0; i < 2; i++) {
                uint32_t rowoff = (uint32_t)(wm * 32 + i * 16 + arow) * 80 +
                                  (uint32_t)(h * 16 + acol8) * 2;
                ldsm4(afh[i], base + XH_OFF + rowoff);
                ldsm4(afl[i], base + XL_OFF + rowoff);
            }
            uint32_t bfh[4][4], bfl[4][4];
#pragma unroll
            for (int j = 0; j < 4; j++) {
                uint32_t rowoff = (uint32_t)(wn * 64 + j * 16 + brow) * 80 +
                                  (uint32_t)(h * 16 + bcol8) * 2;
                ldsm4(bfh[j], base + MH_OFF + rowoff);
                ldsm4(bfl[j], base + ML_OFF + rowoff);
            }
#pragma unroll
            for (int i = 0; i < 2; i++)
#pragma unroll
                for (int j = 0; j < 4; j++) {
                    mma16816(acc[i][2 * j],     afh[i], bfh[j][0], bfh[j][1]);
                    mma16816(acc[i][2 * j + 1], afh[i], bfh[j][2], bfh[j][3]);
                    mma16816(acc[i][2 * j],     afh[i], bfl[j][0], bfl[j][1]);
                    mma16816(acc[i][2 * j + 1], afh[i], bfl[j][2], bfl[j][3]);
                    mma16816(acc[i][2 * j],     afl[i], bfh[j][0], bfh[j][1]);
                    mma16816(acc[i][2 * j + 1], afl[i], bfh[j][2], bfh[j][3]);
                }
        }
        if (kt + 1 < NKT) store_x(cur ^ 1, xnext);
        __syncthreads();
    }

    // epilogue: add bias, store fp32
    int g = lane >> 2, t4 = lane & 3;
#pragma unroll
    for (int i = 0; i < 2; i++) {
        int r0 = by * 64 + wm * 32 + i * 16 + g;
#pragma unroll
        for (int n = 0; n < 8; n++) {
            int coll = wn * 64 + n * 8 + 2 * t4;
            int colg = bx * 256 + coll;
            float bx0 = sb[coll], bx1 = sb[coll + 1];
            float2 v0 = make_float2(acc[i][n][0] + bx0, acc[i][n][1] + bx1);
            float2 v1 = make_float2(acc[i][n][2] + bx0, acc[i][n][3] + bx1);
            *(float2*)(outf + (size_t)r0 * DD + colg) = v0;
            *(float2*)(outf + (size_t)(r0 + 8) * DD + colg) = v1;
        }
    }
}

// ---------------------------------------------------------------------------
// Attend (unchanged): one warp per row, streams keys+values once. 81% DRAM.
// ---------------------------------------------------------------------------
__global__ __launch_bounds__(256) void attend(const float* __restrict__ x,
                                              const float* __restrict__ keys,
                                              const float* __restrict__ values,
                                              float* __restrict__ out) {
    int warp = (blockIdx.x * blockDim.x + threadIdx.x) >> 5;
    int lane = threadIdx.x & 31;
    if (warp >= BSZ) return;

    const float4* xr  = (const float4*)(x + (size_t)warp * DD);
    const float4* q2r = (const float4*)(g_q2 + (size_t)warp * DD);
    const float4* kb  = (const float4*)(keys + (size_t)warp * KN * DD);
    const float4* vb  = (const float4*)(values + (size_t)warp * KN * DD);
    const float4* ur  = (const float4*)g_u;

    float4 xv[4], qv[4];
#pragma unroll
    for (int i = 0; i < 4; i++) {
        xv[i] = xr[lane + 32 * i];
        qv[i] = q2r[lane + 32 * i];
    }

    float qb = 0.f;
#pragma unroll
    for (int i = 0; i < 4; i++) {
        float4 uv = ur[lane + 32 * i];
        qb += xv[i].x * uv.x + xv[i].y * uv.y + xv[i].z * uv.z + xv[i].w * uv.w;
    }
#pragma unroll
    for (int o = 16; o > 0; o >>= 1) qb += __shfl_xor_sync(0xFFFFFFFFu, qb, o);
    qb += g_s0;

    const float scale = 0.044194173824159216f;  // 1/sqrt(512)

    float myscore = 0.f;
    float4 cur[4];
#pragma unroll
    for (int i = 0; i < 4; i++) cur[i] = kb[lane + 32 * i];

#pragma unroll
    for (int k = 0; k < KN; k++) {
        float4 nxt[4];
        if (k + 1 < KN) {
#pragma unroll
            for (int i = 0; i < 4; i++) nxt[i] = kb[(k + 1) * 128 + lane + 32 * i];
        }
        float p = 0.f;
#pragma unroll
        for (int i = 0; i < 4; i++) {
            p += qv[i].x * cur[i].x + qv[i].y * cur[i].y +
                 qv[i].z * cur[i].z + qv[i].w * cur[i].w;
        }
#pragma unroll
        for (int o = 16; o > 0; o >>= 1) p += __shfl_xor_sync(0xFFFFFFFFu, p, o);
        float s = (p + qb) * scale;
        if (lane == k) myscore = s;
#pragma unroll
        for (int i = 0; i < 4; i++) cur[i] = nxt[i];
    }

    float m = myscore;
#pragma unroll
    for (int o = 16; o > 0; o >>= 1)
        m = fmaxf(m, __shfl_xor_sync(0xFFFFFFFFu, m, o));
    float e = expf(myscore - m);
    float sum = e;
#pragma unroll
    for (int o = 16; o > 0; o >>= 1) sum += __shfl_xor_sync(0xFFFFFFFFu, sum, o);
    float a = e / sum;

    float4 acc[4];
#pragma unroll
    for (int i = 0; i < 4; i++) acc[i] = make_float4(0.f, 0.f, 0.f, 0.f);

#pragma unroll
    for (int k = 0; k < KN; k++) {
        float w = __shfl_sync(0xFFFFFFFFu, a, k);
#pragma unroll
        for (int i = 0; i < 4; i++) {
            float4 vv = vb[k * 128 + lane + 32 * i];
            acc[i].x += w * vv.x;
            acc[i].y += w * vv.y;
            acc[i].z += w * vv.z;
            acc[i].w += w * vv.w;
        }
    }

    float4* outr = (float4*)(out + (size_t)warp * DD);
#pragma unroll
    for (int i = 0; i < 4; i++) {
        float4 o;
        o.x = 0.5f * xv[i].x + 0.5f * acc[i].x;
        o.y = 0.5f * xv[i].y + 0.5f * acc[i].y;
        o.z = 0.5f * xv[i].z + 0.5f * acc[i].z;
        o.w = 0.5f * xv[i].w + 0.5f * acc[i].w;
        outr[lane + 32 * i] = o;
    }
}

// ---------------------------------------------------------------------------
extern "C" void kernel_launch(void* const* d_in, const int* in_sizes, int n_in,
                              void* d_out, int out_size) {
    const float* x      = (const float*)d_in[0];
    const float* keys   = (const float*)d_in[1];
    const float* values = (const float*)d_in[2];
    const float* w1     = (const float*)d_in[3];
    const float* b1     = (const float*)d_in[4];
    const float* w2     = (const float*)d_in[5];
    const float* b2     = (const float*)d_in[6];
    float* out = (float*)d_out;

    cudaFuncSetAttribute(gemm_fused, cudaFuncAttributeMaxDynamicSharedMemorySize,
                         GSMEM_TOTAL);

    __nv_bfloat16 *Mth, *Mtl;
    float *q2;
    cudaGetSymbolAddress((void**)&Mth, g_Mth);
    cudaGetSymbolAddress((void**)&Mtl, g_Mtl);
    cudaGetSymbolAddress((void**)&q2, g_q2);

    precompute_all<<<dim3(8, 8), 256>>>(w1, w2, b1, b2);
    gemm_fused<<<dim3(2, 128), 256, GSMEM_TOTAL>>>(x, Mth, Mtl, q2);
    attend<<<(BSZ * 32) / 256, 256>>>(x, keys, values, out);
}

// round 10
// speedup vs baseline: 1.5798x; 1.0434x over previous
#include <cuda_runtime.h>
#include <cuda_bf16.h>
#include <math.h>
#include <stdint.h>

#define BSZ 8192
#define KN  32
#define DD  512

// ---------------------------------------------------------------------------
// Device scratch
// ---------------------------------------------------------------------------
__device__ __nv_bfloat16 g_Mth[DD * DD];   // bf16 hi of Mt[d][j] = sum_e w1[e][j] w2[e][d]
__device__ __nv_bfloat16 g_Mtl[DD * DD];   // bf16 lo
__device__ float g_q2[BSZ * DD];           // x @ M + c
__device__ float g_c[DD];                  // b1 @ w2
__device__ float g_u[DD];                  // b2 @ w1
__device__ float g_s0;                     // b1 . b2

// ---------------------------------------------------------------------------
// Helpers
// ---------------------------------------------------------------------------
__device__ __forceinline__ uint32_t smem_u32(const void* p) {
    uint32_t a;
    asm("{ .reg .u64 t; cvta.to.shared.u64 t, %1; cvt.u32.u64 %0, t; }"
        : "=r"(a) : "l"(p));
    return a;
}
__device__ __forceinline__ void cp16(uint32_t saddr, const void* g) {
    asm volatile("cp.async.cg.shared.global [%0], [%1], 16;"
                 :: "r"(saddr), "l"(g));
}
__device__ __forceinline__ void ldsm4(uint32_t* r, uint32_t addr) {
    asm volatile("ldmatrix.sync.aligned.m8n8.x4.shared.b16 {%0,%1,%2,%3}, [%4];"
                 : "=r"(r[0]), "=r"(r[1]), "=r"(r[2]), "=r"(r[3]) : "r"(addr));
}
__device__ __forceinline__ void mma16816(float* c, const uint32_t* a,
                                         uint32_t b0, uint32_t b1) {
    asm volatile(
        "mma.sync.aligned.m16n8k16.row.col.f32.bf16.bf16.f32 "
        "{%0,%1,%2,%3}, {%4,%5,%6,%7}, {%8,%9}, {%0,%1,%2,%3};"
        : "+f"(c[0]), "+f"(c[1]), "+f"(c[2]), "+f"(c[3])
        : "r"(a[0]), "r"(a[1]), "r"(a[2]), "r"(a[3]), "r"(b0), "r"(b1));
}

// ---------------------------------------------------------------------------
// precompute_all: cp.async double-buffered register-tiled fp32 GEMM.
//   Mt[d][j] = sum_e w1[e][j] * w2[e][d]  -> bf16 hi/lo split store
// Tile 32(d) x 64(j), grid (8, 16) = 128 blocks, 256 threads, 2x4 per thread.
// Fused borders: u[j] (by==0, tid<64), c[d] (bx==0, tid 64..95), s0 (0,0).
// ---------------------------------------------------------------------------
__global__ __launch_bounds__(256) void precompute_all(
    const float* __restrict__ w1, const float* __restrict__ w2,
    const float* __restrict__ b1, const float* __restrict__ b2) {
    __shared__ float s1[2][32][64];   // w1 [e][j]
    __shared__ float s2[2][32][32];   // w2 [e][d]
    __shared__ float sb1[DD], sb2[DD];
    int tid = threadIdx.x;
    int jg = tid & 15;                // j quad (4 cols)
    int dg = tid >> 4;                // d pair (2 rows)
    int j0 = blockIdx.x * 64, d0 = blockIdx.y * 32;

    sb1[tid] = b1[tid]; sb1[tid + 256] = b1[tid + 256];
    sb2[tid] = b2[tid]; sb2[tid + 256] = b2[tid + 256];

    uint32_t s1b = smem_u32(&s1[0][0][0]);
    uint32_t s2b = smem_u32(&s2[0][0][0]);

    auto load_tile = [&](int st, int e0) {
        // s1: 32 rows x 16 float4 = 512 -> 2 per thread
        {
            int r = tid >> 4, q = tid & 15;
#pragma unroll
            for (int i = 0; i < 2; i++) {
                int rr = r + 16 * i;
                cp16(s1b + (uint32_t)((st * 32 + rr) * 64 + q * 4) * 4,
                     w1 + (size_t)(e0 + rr) * DD + j0 + q * 4);
            }
        }
        // s2: 32 rows x 8 float4 = 256 -> 1 per thread
        {
            int r = tid >> 3, q = tid & 7;
            cp16(s2b + (uint32_t)((st * 32 + r) * 32 + q * 4) * 4,
                 w2 + (size_t)(e0 + r) * DD + d0 + q * 4);
        }
        asm volatile("cp.async.commit_group;" ::: "memory");
    };

    float acc[2][4];
#pragma unroll
    for (int r = 0; r < 2; r++)
#pragma unroll
        for (int c = 0; c < 4; c++) acc[r][c] = 0.f;
    float uacc = 0.f, cacc = 0.f;

    load_tile(0, 0);

#pragma unroll 1
    for (int t = 0; t < 16; t++) {
        int st = t & 1;
        if (t + 1 < 16) {
            load_tile(st ^ 1, (t + 1) * 32);
            asm volatile("cp.async.wait_group 1;" ::: "memory");
        } else {
            asm volatile("cp.async.wait_group 0;" ::: "memory");
        }
        __syncthreads();
#pragma unroll
        for (int e = 0; e < 32; e++) {
            float4 bv = *(const float4*)&s1[st][e][jg * 4];
            float a0 = s2[st][e][dg * 2];
            float a1 = s2[st][e][dg * 2 + 1];
            acc[0][0] += a0 * bv.x; acc[0][1] += a0 * bv.y;
            acc[0][2] += a0 * bv.z; acc[0][3] += a0 * bv.w;
            acc[1][0] += a1 * bv.x; acc[1][1] += a1 * bv.y;
            acc[1][2] += a1 * bv.z; acc[1][3] += a1 * bv.w;
        }
        if (blockIdx.y == 0 && tid < 64) {
            int e0 = t * 32;
#pragma unroll
            for (int e = 0; e < 32; e++) uacc += sb2[e0 + e] * s1[st][e][tid];
        }
        if (blockIdx.x == 0 && tid >= 64 && tid < 96) {
            int e0 = t * 32;
#pragma unroll
            for (int e = 0; e < 32; e++) cacc += sb1[e0 + e] * s2[st][e][tid - 64];
        }
        __syncthreads();
    }

#pragma unroll
    for (int r = 0; r < 2; r++) {
        int d = d0 + dg * 2 + r;
        __nv_bfloat16 hv[4], lv[4];
#pragma unroll
        for (int c = 0; c < 4; c++) {
            hv[c] = __float2bfloat16(acc[r][c]);
            lv[c] = __float2bfloat16(acc[r][c] - __bfloat162float(hv[c]));
        }
        *(uint2*)&g_Mth[(size_t)d * DD + j0 + jg * 4] = *(uint2*)hv;
        *(uint2*)&g_Mtl[(size_t)d * DD + j0 + jg * 4] = *(uint2*)lv;
    }
    if (blockIdx.y == 0 && tid < 64) g_u[j0 + tid] = uacc;
    if (blockIdx.x == 0 && tid >= 64 && tid < 96) g_c[d0 + tid - 64] = cacc;
    if (blockIdx.x == 0 && blockIdx.y == 0 && tid < 32) {
        float v = 0.f;
#pragma unroll
        for (int q = 0; q < 16; q++) v += sb1[tid + 32 * q] * sb2[tid + 32 * q];
#pragma unroll
        for (int o = 16; o > 0; o >>= 1) v += __shfl_xor_sync(0xFFFFFFFFu, v, o);
        if (tid == 0) g_s0 = v;
    }
}

// ---------------------------------------------------------------------------
// Fused-split bf16x3 GEMM: q2 = x @ M + c over physical K=512 (16 k32 tiles).
// Block tile 128x256, 512 threads = 16 warps (4m x 4n), warp tile 32x64.
// B fragments processed in j-pairs to keep live regs <= ~120 (no spills).
// Grid (2, 64) = 128 blocks, 1 block/SM, 80B-padded smem rows.
// ---------------------------------------------------------------------------
#define NKT 16
#define XH_OFF 0
#define XL_OFF 10240
#define MH_OFF 20480
#define ML_OFF 40960
#define STAGE_STRIDE 61440
#define GSMEM_TOTAL (2 * STAGE_STRIDE + 1024)

__global__ __launch_bounds__(512, 1) void gemm_fused(
    const float* __restrict__ x,
    const __nv_bfloat16* __restrict__ Mth, const __nv_bfloat16* __restrict__ Mtl,
    float* __restrict__ outf) {
    extern __shared__ char smem[];
    uint32_t sbase = smem_u32(smem);
    int tid = threadIdx.x;
    int lane = tid & 31;
    int warp = tid >> 5;
    int wm = warp >> 2;            // 0..3 (32-row warp tiles)
    int wn = warp & 3;             // 0..3 (64-col warp tiles)
    int bx = blockIdx.x, by = blockIdx.y;

    float* sb = (float*)(smem + 2 * STAGE_STRIDE);
    if (tid < 256) sb[tid] = g_c[bx * 256 + tid];

    float acc[2][8][4];
#pragma unroll
    for (int i = 0; i < 2; i++)
#pragma unroll
        for (int n = 0; n < 8; n++)
#pragma unroll
            for (int q = 0; q < 4; q++) acc[i][n][q] = 0.f;

    int arow  = lane & 15;
    int acol8 = (lane >> 4) * 8;
    int brow  = (lane & 7) + ((lane >> 4) << 3);
    int bcol8 = ((lane >> 3) & 1) * 8;

    // M tiles: 256 rows x 4 x 16B chunks = 1024 cp16 per matrix -> 2/thread
    auto load_M = [&](int stage, int kt) {
        int kk = kt * 32;
        uint32_t mh = sbase + stage * STAGE_STRIDE + MH_OFF;
        uint32_t ml = sbase + stage * STAGE_STRIDE + ML_OFF;
#pragma unroll
        for (int i = 0; i < 2; i++) {
            int c = tid + 512 * i;
            int n = c >> 2, q = c & 3;
            cp16(mh + n * 80 + q * 16,
                 Mth + (size_t)(bx * 256 + n) * DD + kk + q * 8);
            cp16(ml + n * 80 + q * 16,
                 Mtl + (size_t)(bx * 256 + n) * DD + kk + q * 8);
        }
        asm volatile("cp.async.commit_group;" ::: "memory");
    };

    // x: 128 rows x 32 floats; thread -> row tid>>2, chunk tid&3 (8 floats)
    auto load_x_regs = [&](int kt, float4* vr) {
        int kk = kt * 32;
        int r = tid >> 2, q = tid & 3;
        vr[0] = *(const float4*)(x + (size_t)(by * 128 + r) * DD + kk + q * 8);
        vr[1] = *(const float4*)(x + (size_t)(by * 128 + r) * DD + kk + q * 8 + 4);
    };

    auto store_x = [&](int stage, const float4* vr) {
        uint32_t xh = stage * STAGE_STRIDE + XH_OFF;
        uint32_t xl = stage * STAGE_STRIDE + XL_OFF;
        int r = tid >> 2, q = tid & 3;
        float4 v0 = vr[0], v1 = vr[1];
        __nv_bfloat162 h01 = __floats2bfloat162_rn(v0.x, v0.y);
        __nv_bfloat162 h23 = __floats2bfloat162_rn(v0.z, v0.w);
        __nv_bfloat162 h45 = __floats2bfloat162_rn(v1.x, v1.y);
        __nv_bfloat162 h67 = __floats2bfloat162_rn(v1.z, v1.w);
        __nv_bfloat162 l01 = __floats2bfloat162_rn(v0.x - __bfloat162float(h01.x),
                                                   v0.y - __bfloat162float(h01.y));
        __nv_bfloat162 l23 = __floats2bfloat162_rn(v0.z - __bfloat162float(h23.x),
                                                   v0.w - __bfloat162float(h23.y));
        __nv_bfloat162 l45 = __floats2bfloat162_rn(v1.x - __bfloat162float(h45.x),
                                                   v1.y - __bfloat162float(h45.y));
        __nv_bfloat162 l67 = __floats2bfloat162_rn(v1.z - __bfloat162float(h67.x),
                                                   v1.w - __bfloat162float(h67.y));
        union { __nv_bfloat162 b[4]; uint4 u; } ph, pl;
        ph.b[0] = h01; ph.b[1] = h23; ph.b[2] = h45; ph.b[3] = h67;
        pl.b[0] = l01; pl.b[1] = l23; pl.b[2] = l45; pl.b[3] = l67;
        *(uint4*)(smem + xh + r * 80 + q * 16) = ph.u;
        *(uint4*)(smem + xl + r * 80 + q * 16) = pl.u;
    };

    float4 xcur[2];
    load_x_regs(0, xcur);
    load_M(0, 0);
    store_x(0, xcur);

#pragma unroll 1
    for (int kt = 0; kt < NKT; kt++) {
        int cur = kt & 1;
        float4 xnext[2];
        if (kt + 1 < NKT) {
            load_x_regs(kt + 1, xnext);
            load_M(cur ^ 1, kt + 1);
            asm volatile("cp.async.wait_group 1;" ::: "memory");
        } else {
            asm volatile("cp.async.wait_group 0;" ::: "memory");
        }
        __syncthreads();

        uint32_t base = sbase + cur * STAGE_STRIDE;
#pragma unroll
        for (int h = 0; h < 2; h++) {
            uint32_t afh[2][4], afl[2][4];
#pragma unroll
            for (int i = 0; i < 2; i++) {
                uint32_t rowoff = (uint32_t)(wm * 32 + i * 16 + arow) * 80 +
                                  (uint32_t)(h * 16 + acol8) * 2;
                ldsm4(afh[i], base + XH_OFF + rowoff);
                ldsm4(afl[i], base + XL_OFF + rowoff);
            }
            // j-pairs: only 2 B hi + 2 B lo fragment sets live at a time
#pragma unroll
            for (int jp = 0; jp < 2; jp++) {
                uint32_t bfh[2][4], bfl[2][4];
#pragma unroll
                for (int jj = 0; jj < 2; jj++) {
                    int j = jp * 2 + jj;
                    uint32_t rowoff = (uint32_t)(wn * 64 + j * 16 + brow) * 80 +
                                      (uint32_t)(h * 16 + bcol8) * 2;
                    ldsm4(bfh[jj], base + MH_OFF + rowoff);
                    ldsm4(bfl[jj], base + ML_OFF + rowoff);
                }
#pragma unroll
                for (int i = 0; i < 2; i++)
#pragma unroll
                    for (int jj = 0; jj < 2; jj++) {
                        int n = jp * 4 + 2 * jj;
                        mma16816(acc[i][n],     afh[i], bfh[jj][0], bfh[jj][1]);
                        mma16816(acc[i][n + 1], afh[i], bfh[jj][2], bfh[jj][3]);
                        mma16816(acc[i][n],     afh[i], bfl[jj][0], bfl[jj][1]);
                        mma16816(acc[i][n + 1], afh[i], bfl[jj][2], bfl[jj][3]);
                        mma16816(acc[i][n],     afl[i], bfh[jj][0], bfh[jj][1]);
                        mma16816(acc[i][n + 1], afl[i], bfh[jj][2], bfh[jj][3]);
                    }
            }
        }
        if (kt + 1 < NKT) store_x(cur ^ 1, xnext);
        __syncthreads();
    }

    // epilogue: add bias, store fp32
    int g = lane >> 2, t4 = lane & 3;
#pragma unroll
    for (int i = 0; i < 2; i++) {
        int r0 = by * 128 + wm * 32 + i * 16 + g;
#pragma unroll
        for (int n = 0; n < 8; n++) {
            int coll = wn * 64 + n * 8 + 2 * t4;
            int colg = bx * 256 + coll;
            float bx0 = sb[coll], bx1 = sb[coll + 1];
            float2 v0 = make_float2(acc[i][n][0] + bx0, acc[i][n][1] + bx1);
            float2 v1 = make_float2(acc[i][n][2] + bx0, acc[i][n][3] + bx1);
            *(float2*)(outf + (size_t)r0 * DD + colg) = v0;
            *(float2*)(outf + (size_t)(r0 + 8) * DD + colg) = v1;
        }
    }
}

// ---------------------------------------------------------------------------
// Attend (unchanged): one warp per row, streams keys+values once. 81% DRAM.
// ---------------------------------------------------------------------------
__global__ __launch_bounds__(256) void attend(const float* __restrict__ x,
                                              const float* __restrict__ keys,
                                              const float* __restrict__ values,
                                              float* __restrict__ out) {
    int warp = (blockIdx.x * blockDim.x + threadIdx.x) >> 5;
    int lane = threadIdx.x & 31;
    if (warp >= BSZ) return;

    const float4* xr  = (const float4*)(x + (size_t)warp * DD);
    const float4* q2r = (const float4*)(g_q2 + (size_t)warp * DD);
    const float4* kb  = (const float4*)(keys + (size_t)warp * KN * DD);
    const float4* vb  = (const float4*)(values + (size_t)warp * KN * DD);
    const float4* ur  = (const float4*)g_u;

    float4 xv[4], qv[4];
#pragma unroll
    for (int i = 0; i < 4; i++) {
        xv[i] = xr[lane + 32 * i];
        qv[i] = q2r[lane + 32 * i];
    }

    float qb = 0.f;
#pragma unroll
    for (int i = 0; i < 4; i++) {
        float4 uv = ur[lane + 32 * i];
        qb += xv[i].x * uv.x + xv[i].y * uv.y + xv[i].z * uv.z + xv[i].w * uv.w;
    }
#pragma unroll
    for (int o = 16; o > 0; o >>= 1) qb += __shfl_xor_sync(0xFFFFFFFFu, qb, o);
    qb += g_s0;

    const float scale = 0.044194173824159216f;  // 1/sqrt(512)

    float myscore = 0.f;
    float4 cur[4];
#pragma unroll
    for (int i = 0; i < 4; i++) cur[i] = kb[lane + 32 * i];

#pragma unroll
    for (int k = 0; k < KN; k++) {
        float4 nxt[4];
        if (k + 1 < KN) {
#pragma unroll
            for (int i = 0; i < 4; i++) nxt[i] = kb[(k + 1) * 128 + lane + 32 * i];
        }
        float p = 0.f;
#pragma unroll
        for (int i = 0; i < 4; i++) {
            p += qv[i].x * cur[i].x + qv[i].y * cur[i].y +
                 qv[i].z * cur[i].z + qv[i].w * cur[i].w;
        }
#pragma unroll
        for (int o = 16; o > 0; o >>= 1) p += __shfl_xor_sync(0xFFFFFFFFu, p, o);
        float s = (p + qb) * scale;
        if (lane == k) myscore = s;
#pragma unroll
        for (int i = 0; i < 4; i++) cur[i] = nxt[i];
    }

    float m = myscore;
#pragma unroll
    for (int o = 16; o > 0; o >>= 1)
        m = fmaxf(m, __shfl_xor_sync(0xFFFFFFFFu, m, o));
    float e = expf(myscore - m);
    float sum = e;
#pragma unroll
    for (int o = 16; o > 0; o >>= 1) sum += __shfl_xor_sync(0xFFFFFFFFu, sum, o);
    float a = e / sum;

    float4 acc[4];
#pragma unroll
    for (int i = 0; i < 4; i++) acc[i] = make_float4(0.f, 0.f, 0.f, 0.f);

#pragma unroll
    for (int k = 0; k < KN; k++) {
        float w = __shfl_sync(0xFFFFFFFFu, a, k);
#pragma unroll
        for (int i = 0; i < 4; i++) {
            float4 vv = vb[k * 128 + lane + 32 * i];
            acc[i].x += w * vv.x;
            acc[i].y += w * vv.y;
            acc[i].z += w * vv.z;
            acc[i].w += w * vv.w;
        }
    }

    float4* outr = (float4*)(out + (size_t)warp * DD);
#pragma unroll
    for (int i = 0; i < 4; i++) {
        float4 o;
        o.x = 0.5f * xv[i].x + 0.5f * acc[i].x;
        o.y = 0.5f * xv[i].y + 0.5f * acc[i].y;
        o.z = 0.5f * xv[i].z + 0.5f * acc[i].z;
        o.w = 0.5f * xv[i].w + 0.5f * acc[i].w;
        outr[lane + 32 * i] = o;
    }
}

// ---------------------------------------------------------------------------
extern "C" void kernel_launch(void* const* d_in, const int* in_sizes, int n_in,
                              void* d_out, int out_size) {
    const float* x      = (const float*)d_in[0];
    const float* keys   = (const float*)d_in[1];
    const float* values = (const float*)d_in[2];
    const float* w1     = (const float*)d_in[3];
    const float* b1     = (const float*)d_in[4];
    const float* w2     = (const float*)d_in[5];
    const float* b2     = (const float*)d_in[6];
    float* out = (float*)d_out;

    cudaFuncSetAttribute(gemm_fused, cudaFuncAttributeMaxDynamicSharedMemorySize,
                         GSMEM_TOTAL);

    __nv_bfloat16 *Mth, *Mtl;
    float *q2;
    cudaGetSymbolAddress((void**)&Mth, g_Mth);
    cudaGetSymbolAddress((void**)&Mtl, g_Mtl);
    cudaGetSymbolAddress((void**)&q2, g_q2);

    precompute_all<<<dim3(8, 16), 256>>>(w1, w2, b1, b2);
    gemm_fused<<<dim3(2, 64), 512, GSMEM_TOTAL>>>(x, Mth, Mtl, q2);
    attend<<<(BSZ * 32) / 256, 256>>>(x, keys, values, out);
}

// round 11
// speedup vs baseline: 1.6625x; 1.0523x over previous
#include <cuda_runtime.h>
#include <cuda_bf16.h>
#include <math.h>
#include <stdint.h>

#define BSZ 8192
#define KN  32
#define DD  512

// ---------------------------------------------------------------------------
// Device scratch
// ---------------------------------------------------------------------------
__device__ __nv_bfloat16 g_Mth[DD * DD];   // bf16 hi of Mt[d][j] = sum_e w1[e][j] w2[e][d]
__device__ __nv_bfloat16 g_Mtl[DD * DD];   // bf16 lo
__device__ float g_q2[BSZ * DD];           // x @ M + c
__device__ float g_c[DD];                  // b1 @ w2
__device__ float g_u[DD];                  // b2 @ w1
__device__ float g_s0;                     // b1 . b2

// ---------------------------------------------------------------------------
// Helpers
// ---------------------------------------------------------------------------
__device__ __forceinline__ uint32_t smem_u32(const void* p) {
    uint32_t a;
    asm("{ .reg .u64 t; cvta.to.shared.u64 t, %1; cvt.u32.u64 %0, t; }"
        : "=r"(a) : "l"(p));
    return a;
}
__device__ __forceinline__ void cp16(uint32_t saddr, const void* g) {
    asm volatile("cp.async.cg.shared.global [%0], [%1], 16;"
                 :: "r"(saddr), "l"(g));
}
__device__ __forceinline__ void ldsm4(uint32_t* r, uint32_t addr) {
    asm volatile("ldmatrix.sync.aligned.m8n8.x4.shared.b16 {%0,%1,%2,%3}, [%4];"
                 : "=r"(r[0]), "=r"(r[1]), "=r"(r[2]), "=r"(r[3]) : "r"(addr));
}
__device__ __forceinline__ void mma16816(float* c, const uint32_t* a,
                                         uint32_t b0, uint32_t b1) {
    asm volatile(
        "mma.sync.aligned.m16n8k16.row.col.f32.bf16.bf16.f32 "
        "{%0,%1,%2,%3}, {%4,%5,%6,%7}, {%8,%9}, {%0,%1,%2,%3};"
        : "+f"(c[0]), "+f"(c[1]), "+f"(c[2]), "+f"(c[3])
        : "r"(a[0]), "r"(a[1]), "r"(a[2]), "r"(a[3]), "r"(b0), "r"(b1));
}
__device__ __forceinline__ float4 ldcs4(const float4* p) {
    float4 v;
    asm volatile("ld.global.cs.v4.f32 {%0,%1,%2,%3}, [%4];"
                 : "=f"(v.x), "=f"(v.y), "=f"(v.z), "=f"(v.w) : "l"(p));
    return v;
}

// ---------------------------------------------------------------------------
// precompute_all: cp.async double-buffered register-tiled fp32 GEMM.
//   Mt[d][j] = sum_e w1[e][j] * w2[e][d]  -> bf16 hi/lo split store
// Tile 32(d) x 64(j), grid (8, 16) = 128 blocks, 256 threads, 2x4 per thread.
// Fused borders: u[j] (by==0, tid<64), c[d] (bx==0, tid 64..95), s0 (0,0).
// ---------------------------------------------------------------------------
__global__ __launch_bounds__(256) void precompute_all(
    const float* __restrict__ w1, const float* __restrict__ w2,
    const float* __restrict__ b1, const float* __restrict__ b2) {
    __shared__ float s1[2][32][64];   // w1 [e][j]
    __shared__ float s2[2][32][32];   // w2 [e][d]
    __shared__ float sb1[DD], sb2[DD];
    int tid = threadIdx.x;
    int jg = tid & 15;                // j quad (4 cols)
    int dg = tid >> 4;                // d pair (2 rows)
    int j0 = blockIdx.x * 64, d0 = blockIdx.y * 32;

    sb1[tid] = b1[tid]; sb1[tid + 256] = b1[tid + 256];
    sb2[tid] = b2[tid]; sb2[tid + 256] = b2[tid + 256];

    uint32_t s1b = smem_u32(&s1[0][0][0]);
    uint32_t s2b = smem_u32(&s2[0][0][0]);

    auto load_tile = [&](int st, int e0) {
        {
            int r = tid >> 4, q = tid & 15;
#pragma unroll
            for (int i = 0; i < 2; i++) {
                int rr = r + 16 * i;
                cp16(s1b + (uint32_t)((st * 32 + rr) * 64 + q * 4) * 4,
                     w1 + (size_t)(e0 + rr) * DD + j0 + q * 4);
            }
        }
        {
            int r = tid >> 3, q = tid & 7;
            cp16(s2b + (uint32_t)((st * 32 + r) * 32 + q * 4) * 4,
                 w2 + (size_t)(e0 + r) * DD + d0 + q * 4);
        }
        asm volatile("cp.async.commit_group;" ::: "memory");
    };

    float acc[2][4];
#pragma unroll
    for (int r = 0; r < 2; r++)
#pragma unroll
        for (int c = 0; c < 4; c++) acc[r][c] = 0.f;
    float uacc = 0.f, cacc = 0.f;

    load_tile(0, 0);

#pragma unroll 1
    for (int t = 0; t < 16; t++) {
        int st = t & 1;
        if (t + 1 < 16) {
            load_tile(st ^ 1, (t + 1) * 32);
            asm volatile("cp.async.wait_group 1;" ::: "memory");
        } else {
            asm volatile("cp.async.wait_group 0;" ::: "memory");
        }
        __syncthreads();
#pragma unroll
        for (int e = 0; e < 32; e++) {
            float4 bv = *(const float4*)&s1[st][e][jg * 4];
            float a0 = s2[st][e][dg * 2];
            float a1 = s2[st][e][dg * 2 + 1];
            acc[0][0] += a0 * bv.x; acc[0][1] += a0 * bv.y;
            acc[0][2] += a0 * bv.z; acc[0][3] += a0 * bv.w;
            acc[1][0] += a1 * bv.x; acc[1][1] += a1 * bv.y;
            acc[1][2] += a1 * bv.z; acc[1][3] += a1 * bv.w;
        }
        if (blockIdx.y == 0 && tid < 64) {
            int e0 = t * 32;
#pragma unroll
            for (int e = 0; e < 32; e++) uacc += sb2[e0 + e] * s1[st][e][tid];
        }
        if (blockIdx.x == 0 && tid >= 64 && tid < 96) {
            int e0 = t * 32;
#pragma unroll
            for (int e = 0; e < 32; e++) cacc += sb1[e0 + e] * s2[st][e][tid - 64];
        }
        __syncthreads();
    }

#pragma unroll
    for (int r = 0; r < 2; r++) {
        int d = d0 + dg * 2 + r;
        __nv_bfloat16 hv[4], lv[4];
#pragma unroll
        for (int c = 0; c < 4; c++) {
            hv[c] = __float2bfloat16(acc[r][c]);
            lv[c] = __float2bfloat16(acc[r][c] - __bfloat162float(hv[c]));
        }
        *(uint2*)&g_Mth[(size_t)d * DD + j0 + jg * 4] = *(uint2*)hv;
        *(uint2*)&g_Mtl[(size_t)d * DD + j0 + jg * 4] = *(uint2*)lv;
    }
    if (blockIdx.y == 0 && tid < 64) g_u[j0 + tid] = uacc;
    if (blockIdx.x == 0 && tid >= 64 && tid < 96) g_c[d0 + tid - 64] = cacc;
    if (blockIdx.x == 0 && blockIdx.y == 0 && tid < 32) {
        float v = 0.f;
#pragma unroll
        for (int q = 0; q < 16; q++) v += sb1[tid + 32 * q] * sb2[tid + 32 * q];
#pragma unroll
        for (int o = 16; o > 0; o >>= 1) v += __shfl_xor_sync(0xFFFFFFFFu, v, o);
        if (tid == 0) g_s0 = v;
    }
}

// ---------------------------------------------------------------------------
// Fused-split bf16x3 GEMM: q2 = x @ M + c over physical K=512 (16 k32 tiles).
// Block tile 128x256, 512 threads = 16 warps (4m x 4n), warp tile 32x64.
// Grid (2, 64) = 128 blocks, 1 block/SM, 80B-padded smem rows.
// ---------------------------------------------------------------------------
#define NKT 16
#define XH_OFF 0
#define XL_OFF 10240
#define MH_OFF 20480
#define ML_OFF 40960
#define STAGE_STRIDE 61440
#define GSMEM_TOTAL (2 * STAGE_STRIDE + 1024)

__global__ __launch_bounds__(512, 1) void gemm_fused(
    const float* __restrict__ x,
    const __nv_bfloat16* __restrict__ Mth, const __nv_bfloat16* __restrict__ Mtl,
    float* __restrict__ outf) {
    extern __shared__ char smem[];
    uint32_t sbase = smem_u32(smem);
    int tid = threadIdx.x;
    int lane = tid & 31;
    int warp = tid >> 5;
    int wm = warp >> 2;            // 0..3 (32-row warp tiles)
    int wn = warp & 3;             // 0..3 (64-col warp tiles)
    int bx = blockIdx.x, by = blockIdx.y;

    float* sb = (float*)(smem + 2 * STAGE_STRIDE);
    if (tid < 256) sb[tid] = g_c[bx * 256 + tid];

    float acc[2][8][4];
#pragma unroll
    for (int i = 0; i < 2; i++)
#pragma unroll
        for (int n = 0; n < 8; n++)
#pragma unroll
            for (int q = 0; q < 4; q++) acc[i][n][q] = 0.f;

    int arow  = lane & 15;
    int acol8 = (lane >> 4) * 8;
    int brow  = (lane & 7) + ((lane >> 4) << 3);
    int bcol8 = ((lane >> 3) & 1) * 8;

    auto load_M = [&](int stage, int kt) {
        int kk = kt * 32;
        uint32_t mh = sbase + stage * STAGE_STRIDE + MH_OFF;
        uint32_t ml = sbase + stage * STAGE_STRIDE + ML_OFF;
#pragma unroll
        for (int i = 0; i < 2; i++) {
            int c = tid + 512 * i;
            int n = c >> 2, q = c & 3;
            cp16(mh + n * 80 + q * 16,
                 Mth + (size_t)(bx * 256 + n) * DD + kk + q * 8);
            cp16(ml + n * 80 + q * 16,
                 Mtl + (size_t)(bx * 256 + n) * DD + kk + q * 8);
        }
        asm volatile("cp.async.commit_group;" ::: "memory");
    };

    auto load_x_regs = [&](int kt, float4* vr) {
        int kk = kt * 32;
        int r = tid >> 2, q = tid & 3;
        vr[0] = *(const float4*)(x + (size_t)(by * 128 + r) * DD + kk + q * 8);
        vr[1] = *(const float4*)(x + (size_t)(by * 128 + r) * DD + kk + q * 8 + 4);
    };

    auto store_x = [&](int stage, const float4* vr) {
        uint32_t xh = stage * STAGE_STRIDE + XH_OFF;
        uint32_t xl = stage * STAGE_STRIDE + XL_OFF;
        int r = tid >> 2, q = tid & 3;
        float4 v0 = vr[0], v1 = vr[1];
        __nv_bfloat162 h01 = __floats2bfloat162_rn(v0.x, v0.y);
        __nv_bfloat162 h23 = __floats2bfloat162_rn(v0.z, v0.w);
        __nv_bfloat162 h45 = __floats2bfloat162_rn(v1.x, v1.y);
        __nv_bfloat162 h67 = __floats2bfloat162_rn(v1.z, v1.w);
        __nv_bfloat162 l01 = __floats2bfloat162_rn(v0.x - __bfloat162float(h01.x),
                                                   v0.y - __bfloat162float(h01.y));
        __nv_bfloat162 l23 = __floats2bfloat162_rn(v0.z - __bfloat162float(h23.x),
                                                   v0.w - __bfloat162float(h23.y));
        __nv_bfloat162 l45 = __floats2bfloat162_rn(v1.x - __bfloat162float(h45.x),
                                                   v1.y - __bfloat162float(h45.y));
        __nv_bfloat162 l67 = __floats2bfloat162_rn(v1.z - __bfloat162float(h67.x),
                                                   v1.w - __bfloat162float(h67.y));
        union { __nv_bfloat162 b[4]; uint4 u; } ph, pl;
        ph.b[0] = h01; ph.b[1] = h23; ph.b[2] = h45; ph.b[3] = h67;
        pl.b[0] = l01; pl.b[1] = l23; pl.b[2] = l45; pl.b[3] = l67;
        *(uint4*)(smem + xh + r * 80 + q * 16) = ph.u;
        *(uint4*)(smem + xl + r * 80 + q * 16) = pl.u;
    };

    float4 xcur[2];
    load_x_regs(0, xcur);
    load_M(0, 0);
    store_x(0, xcur);

#pragma unroll 1
    for (int kt = 0; kt < NKT; kt++) {
        int cur = kt & 1;
        float4 xnext[2];
        if (kt + 1 < NKT) {
            load_x_regs(kt + 1, xnext);
            load_M(cur ^ 1, kt + 1);
            asm volatile("cp.async.wait_group 1;" ::: "memory");
        } else {
            asm volatile("cp.async.wait_group 0;" ::: "memory");
        }
        __syncthreads();

        uint32_t base = sbase + cur * STAGE_STRIDE;
#pragma unroll
        for (int h = 0; h < 2; h++) {
            uint32_t afh[2][4], afl[2][4];
#pragma unroll
            for (int i = 0; i < 2; i++) {
                uint32_t rowoff = (uint32_t)(wm * 32 + i * 16 + arow) * 80 +
                                  (uint32_t)(h * 16 + acol8) * 2;
                ldsm4(afh[i], base + XH_OFF + rowoff);
                ldsm4(afl[i], base + XL_OFF + rowoff);
            }
#pragma unroll
            for (int jp = 0; jp < 2; jp++) {
                uint32_t bfh[2][4], bfl[2][4];
#pragma unroll
                for (int jj = 0; jj < 2; jj++) {
                    int j = jp * 2 + jj;
                    uint32_t rowoff = (uint32_t)(wn * 64 + j * 16 + brow) * 80 +
                                      (uint32_t)(h * 16 + bcol8) * 2;
                    ldsm4(bfh[jj], base + MH_OFF + rowoff);
                    ldsm4(bfl[jj], base + ML_OFF + rowoff);
                }
#pragma unroll
                for (int i = 0; i < 2; i++)
#pragma unroll
                    for (int jj = 0; jj < 2; jj++) {
                        int n = jp * 4 + 2 * jj;
                        mma16816(acc[i][n],     afh[i], bfh[jj][0], bfh[jj][1]);
                        mma16816(acc[i][n + 1], afh[i], bfh[jj][2], bfh[jj][3]);
                        mma16816(acc[i][n],     afh[i], bfl[jj][0], bfl[jj][1]);
                        mma16816(acc[i][n + 1], afh[i], bfl[jj][2], bfl[jj][3]);
                        mma16816(acc[i][n],     afl[i], bfh[jj][0], bfh[jj][1]);
                        mma16816(acc[i][n + 1], afl[i], bfh[jj][2], bfh[jj][3]);
                    }
            }
        }
        if (kt + 1 < NKT) store_x(cur ^ 1, xnext);
        __syncthreads();
    }

    int g = lane >> 2, t4 = lane & 3;
#pragma unroll
    for (int i = 0; i < 2; i++) {
        int r0 = by * 128 + wm * 32 + i * 16 + g;
#pragma unroll
        for (int n = 0; n < 8; n++) {
            int coll = wn * 64 + n * 8 + 2 * t4;
            int colg = bx * 256 + coll;
            float bx0 = sb[coll], bx1 = sb[coll + 1];
            float2 v0 = make_float2(acc[i][n][0] + bx0, acc[i][n][1] + bx1);
            float2 v1 = make_float2(acc[i][n][2] + bx0, acc[i][n][3] + bx1);
            *(float2*)(outf + (size_t)r0 * DD + colg) = v0;
            *(float2*)(outf + (size_t)(r0 + 8) * DD + colg) = v1;
        }
    }
}

// ---------------------------------------------------------------------------
// Attend: one warp per row; 128-thread blocks for 5 blocks/SM (20 warps/SM,
// +33% load concurrency vs 256-thr config). Streaming loads (__ldcs /
// ld.global.cs) for the read-once keys/values so they bypass L2 residency.
// ---------------------------------------------------------------------------
__global__ __launch_bounds__(128) void attend(const float* __restrict__ x,
                                              const float* __restrict__ keys,
                                              const float* __restrict__ values,
                                              float* __restrict__ out) {
    int warp = (blockIdx.x * blockDim.x + threadIdx.x) >> 5;
    int lane = threadIdx.x & 31;
    if (warp >= BSZ) return;

    const float4* xr  = (const float4*)(x + (size_t)warp * DD);
    const float4* q2r = (const float4*)(g_q2 + (size_t)warp * DD);
    const float4* kb  = (const float4*)(keys + (size_t)warp * KN * DD);
    const float4* vb  = (const float4*)(values + (size_t)warp * KN * DD);
    const float4* ur  = (const float4*)g_u;

    float4 xv[4], qv[4];
#pragma unroll
    for (int i = 0; i < 4; i++) {
        xv[i] = xr[lane + 32 * i];
        qv[i] = q2r[lane + 32 * i];
    }

    float qb = 0.f;
#pragma unroll
    for (int i = 0; i < 4; i++) {
        float4 uv = ur[lane + 32 * i];
        qb += xv[i].x * uv.x + xv[i].y * uv.y + xv[i].z * uv.z + xv[i].w * uv.w;
    }
#pragma unroll
    for (int o = 16; o > 0; o >>= 1) qb += __shfl_xor_sync(0xFFFFFFFFu, qb, o);
    qb += g_s0;

    const float scale = 0.044194173824159216f;  // 1/sqrt(512)

    float myscore = 0.f;
    float4 cur[4];
#pragma unroll
    for (int i = 0; i < 4; i++) cur[i] = ldcs4(&kb[lane + 32 * i]);

#pragma unroll
    for (int k = 0; k < KN; k++) {
        float4 nxt[4];
        if (k + 1 < KN) {
#pragma unroll
            for (int i = 0; i < 4; i++)
                nxt[i] = ldcs4(&kb[(k + 1) * 128 + lane + 32 * i]);
        }
        float p = 0.f;
#pragma unroll
        for (int i = 0; i < 4; i++) {
            p += qv[i].x * cur[i].x + qv[i].y * cur[i].y +
                 qv[i].z * cur[i].z + qv[i].w * cur[i].w;
        }
#pragma unroll
        for (int o = 16; o > 0; o >>= 1) p += __shfl_xor_sync(0xFFFFFFFFu, p, o);
        float s = (p + qb) * scale;
        if (lane == k) myscore = s;
#pragma unroll
        for (int i = 0; i < 4; i++) cur[i] = nxt[i];
    }

    float m = myscore;
#pragma unroll
    for (int o = 16; o > 0; o >>= 1)
        m = fmaxf(m, __shfl_xor_sync(0xFFFFFFFFu, m, o));
    float e = expf(myscore - m);
    float sum = e;
#pragma unroll
    for (int o = 16; o > 0; o >>= 1) sum += __shfl_xor_sync(0xFFFFFFFFu, sum, o);
    float a = e / sum;

    float4 acc[4];
#pragma unroll
    for (int i = 0; i < 4; i++) acc[i] = make_float4(0.f, 0.f, 0.f, 0.f);

#pragma unroll
    for (int k = 0; k < KN; k++) {
        float w = __shfl_sync(0xFFFFFFFFu, a, k);
#pragma unroll
        for (int i = 0; i < 4; i++) {
            float4 vv = ldcs4(&vb[k * 128 + lane + 32 * i]);
            acc[i].x += w * vv.x;
            acc[i].y += w * vv.y;
            acc[i].z += w * vv.z;
            acc[i].w += w * vv.w;
        }
    }

    float4* outr = (float4*)(out + (size_t)warp * DD);
#pragma unroll
    for (int i = 0; i < 4; i++) {
        float4 o;
        o.x = 0.5f * xv[i].x + 0.5f * acc[i].x;
        o.y = 0.5f * xv[i].y + 0.5f * acc[i].y;
        o.z = 0.5f * xv[i].z + 0.5f * acc[i].z;
        o.w = 0.5f * xv[i].w + 0.5f * acc[i].w;
        outr[lane + 32 * i] = o;
    }
}

// ---------------------------------------------------------------------------
extern "C" void kernel_launch(void* const* d_in, const int* in_sizes, int n_in,
                              void* d_out, int out_size) {
    const float* x      = (const float*)d_in[0];
    const float* keys   = (const float*)d_in[1];
    const float* values = (const float*)d_in[2];
    const float* w1     = (const float*)d_in[3];
    const float* b1     = (const float*)d_in[4];
    const float* w2     = (const float*)d_in[5];
    const float* b2     = (const float*)d_in[6];
    float* out = (float*)d_out;

    cudaFuncSetAttribute(gemm_fused, cudaFuncAttributeMaxDynamicSharedMemorySize,
                         GSMEM_TOTAL);

    __nv_bfloat16 *Mth, *Mtl;
    float *q2;
    cudaGetSymbolAddress((void**)&Mth, g_Mth);
    cudaGetSymbolAddress((void**)&Mtl, g_Mtl);
    cudaGetSymbolAddress((void**)&q2, g_q2);

    precompute_all<<<dim3(8, 16), 256>>>(w1, w2, b1, b2);
    gemm_fused<<<dim3(2, 64), 512, GSMEM_TOTAL>>>(x, Mth, Mtl, q2);
    attend<<<(BSZ * 32) / 128, 128>>>(x, keys, values, out);
}

// round 12
// speedup vs baseline: 1.7251x; 1.0377x over previous
#include <cuda_runtime.h>
#include <cuda_bf16.h>
#include <cuda_fp16.h>
#include <math.h>
#include <stdint.h>

#define BSZ 8192
#define KN  32
#define DD  512

// ---------------------------------------------------------------------------
// Device scratch
// ---------------------------------------------------------------------------
__device__ __half g_Mth[DD * DD];          // fp16 hi of Mt[d][j] = sum_e w1[e][j] w2[e][d]
__device__ __half g_Mtl[DD * DD];          // fp16 lo
__device__ float g_q2[BSZ * DD];           // x @ M + c
__device__ float g_c[DD];                  // b1 @ w2
__device__ float g_u[DD];                  // b2 @ w1
__device__ float g_s0;                     // b1 . b2

// ---------------------------------------------------------------------------
// Helpers
// ---------------------------------------------------------------------------
__device__ __forceinline__ uint32_t smem_u32(const void* p) {
    uint32_t a;
    asm("{ .reg .u64 t; cvta.to.shared.u64 t, %1; cvt.u32.u64 %0, t; }"
        : "=r"(a) : "l"(p));
    return a;
}
__device__ __forceinline__ void cp16(uint32_t saddr, const void* g) {
    asm volatile("cp.async.cg.shared.global [%0], [%1], 16;"
                 :: "r"(saddr), "l"(g));
}
__device__ __forceinline__ void ldsm4(uint32_t* r, uint32_t addr) {
    asm volatile("ldmatrix.sync.aligned.m8n8.x4.shared.b16 {%0,%1,%2,%3}, [%4];"
                 : "=r"(r[0]), "=r"(r[1]), "=r"(r[2]), "=r"(r[3]) : "r"(addr));
}
__device__ __forceinline__ void mma16816h(float* c, const uint32_t* a,
                                          uint32_t b0, uint32_t b1) {
    asm volatile(
        "mma.sync.aligned.m16n8k16.row.col.f32.f16.f16.f32 "
        "{%0,%1,%2,%3}, {%4,%5,%6,%7}, {%8,%9}, {%0,%1,%2,%3};"
        : "+f"(c[0]), "+f"(c[1]), "+f"(c[2]), "+f"(c[3])
        : "r"(a[0]), "r"(a[1]), "r"(a[2]), "r"(a[3]), "r"(b0), "r"(b1));
}
__device__ __forceinline__ float4 ldcs4(const float4* p) {
    float4 v;
    asm volatile("ld.global.cs.v4.f32 {%0,%1,%2,%3}, [%4];"
                 : "=f"(v.x), "=f"(v.y), "=f"(v.z), "=f"(v.w) : "l"(p));
    return v;
}

// ---------------------------------------------------------------------------
// precompute_all: cp.async double-buffered register-tiled fp32 GEMM.
//   Mt[d][j] = sum_e w1[e][j] * w2[e][d]  -> fp16 hi/lo split store
// Tile 32(d) x 64(j), grid (8, 16) = 128 blocks, 256 threads, 2x4 per thread.
// Fused borders: u[j] (by==0, tid<64), c[d] (bx==0, tid 64..95), s0 (0,0).
// ---------------------------------------------------------------------------
__global__ __launch_bounds__(256) void precompute_all(
    const float* __restrict__ w1, const float* __restrict__ w2,
    const float* __restrict__ b1, const float* __restrict__ b2) {
    __shared__ float s1[2][32][64];   // w1 [e][j]
    __shared__ float s2[2][32][32];   // w2 [e][d]
    __shared__ float sb1[DD], sb2[DD];
    int tid = threadIdx.x;
    int jg = tid & 15;                // j quad (4 cols)
    int dg = tid >> 4;                // d pair (2 rows)
    int j0 = blockIdx.x * 64, d0 = blockIdx.y * 32;

    sb1[tid] = b1[tid]; sb1[tid + 256] = b1[tid + 256];
    sb2[tid] = b2[tid]; sb2[tid + 256] = b2[tid + 256];

    uint32_t s1b = smem_u32(&s1[0][0][0]);
    uint32_t s2b = smem_u32(&s2[0][0][0]);

    auto load_tile = [&](int st, int e0) {
        {
            int r = tid >> 4, q = tid & 15;
#pragma unroll
            for (int i = 0; i < 2; i++) {
                int rr = r + 16 * i;
                cp16(s1b + (uint32_t)((st * 32 + rr) * 64 + q * 4) * 4,
                     w1 + (size_t)(e0 + rr) * DD + j0 + q * 4);
            }
        }
        {
            int r = tid >> 3, q = tid & 7;
            cp16(s2b + (uint32_t)((st * 32 + r) * 32 + q * 4) * 4,
                 w2 + (size_t)(e0 + r) * DD + d0 + q * 4);
        }
        asm volatile("cp.async.commit_group;" ::: "memory");
    };

    float acc[2][4];
#pragma unroll
    for (int r = 0; r < 2; r++)
#pragma unroll
        for (int c = 0; c < 4; c++) acc[r][c] = 0.f;
    float uacc = 0.f, cacc = 0.f;

    load_tile(0, 0);

#pragma unroll 1
    for (int t = 0; t < 16; t++) {
        int st = t & 1;
        if (t + 1 < 16) {
            load_tile(st ^ 1, (t + 1) * 32);
            asm volatile("cp.async.wait_group 1;" ::: "memory");
        } else {
            asm volatile("cp.async.wait_group 0;" ::: "memory");
        }
        __syncthreads();
#pragma unroll
        for (int e = 0; e < 32; e++) {
            float4 bv = *(const float4*)&s1[st][e][jg * 4];
            float a0 = s2[st][e][dg * 2];
            float a1 = s2[st][e][dg * 2 + 1];
            acc[0][0] += a0 * bv.x; acc[0][1] += a0 * bv.y;
            acc[0][2] += a0 * bv.z; acc[0][3] += a0 * bv.w;
            acc[1][0] += a1 * bv.x; acc[1][1] += a1 * bv.y;
            acc[1][2] += a1 * bv.z; acc[1][3] += a1 * bv.w;
        }
        if (blockIdx.y == 0 && tid < 64) {
            int e0 = t * 32;
#pragma unroll
            for (int e = 0; e < 32; e++) uacc += sb2[e0 + e] * s1[st][e][tid];
        }
        if (blockIdx.x == 0 && tid >= 64 && tid < 96) {
            int e0 = t * 32;
#pragma unroll
            for (int e = 0; e < 32; e++) cacc += sb1[e0 + e] * s2[st][e][tid - 64];
        }
        __syncthreads();
    }

#pragma unroll
    for (int r = 0; r < 2; r++) {
        int d = d0 + dg * 2 + r;
        __half hv[4], lv[4];
#pragma unroll
        for (int c = 0; c < 4; c++) {
            hv[c] = __float2half(acc[r][c]);
            lv[c] = __float2half(acc[r][c] - __half2float(hv[c]));
        }
        *(uint2*)&g_Mth[(size_t)d * DD + j0 + jg * 4] = *(uint2*)hv;
        *(uint2*)&g_Mtl[(size_t)d * DD + j0 + jg * 4] = *(uint2*)lv;
    }
    if (blockIdx.y == 0 && tid < 64) g_u[j0 + tid] = uacc;
    if (blockIdx.x == 0 && tid >= 64 && tid < 96) g_c[d0 + tid - 64] = cacc;
    if (blockIdx.x == 0 && blockIdx.y == 0 && tid < 32) {
        float v = 0.f;
#pragma unroll
        for (int q = 0; q < 16; q++) v += sb1[tid + 32 * q] * sb2[tid + 32 * q];
#pragma unroll
        for (int o = 16; o > 0; o >>= 1) v += __shfl_xor_sync(0xFFFFFFFFu, v, o);
        if (tid == 0) g_s0 = v;
    }
}

// ---------------------------------------------------------------------------
// fp16 two-product GEMM: q2 = xh @ (Mh + Ml) + c,  K=512 (16 k32 tiles).
// x truncated to fp16 (error 2^-11, randomized over K -> q2 rel ~1e-4);
// M split fp16 hi/lo so M is exact to 2^-22.
// Block tile 128x256, 512 threads = 16 warps (4m x 4n), warp tile 32x64.
// Grid (2, 64) = 128 blocks, 1 block/SM, 80B-padded smem rows.
// ---------------------------------------------------------------------------
#define NKT 16
#define XH_OFF 0
#define MH_OFF 10240
#define ML_OFF 30720
#define STAGE_STRIDE 51200
#define GSMEM_TOTAL (2 * STAGE_STRIDE + 1024)

__global__ __launch_bounds__(512, 1) void gemm_fused(
    const float* __restrict__ x,
    const __half* __restrict__ Mth, const __half* __restrict__ Mtl,
    float* __restrict__ outf) {
    extern __shared__ char smem[];
    uint32_t sbase = smem_u32(smem);
    int tid = threadIdx.x;
    int lane = tid & 31;
    int warp = tid >> 5;
    int wm = warp >> 2;            // 0..3 (32-row warp tiles)
    int wn = warp & 3;             // 0..3 (64-col warp tiles)
    int bx = blockIdx.x, by = blockIdx.y;

    float* sb = (float*)(smem + 2 * STAGE_STRIDE);
    if (tid < 256) sb[tid] = g_c[bx * 256 + tid];

    float acc[2][8][4];
#pragma unroll
    for (int i = 0; i < 2; i++)
#pragma unroll
        for (int n = 0; n < 8; n++)
#pragma unroll
            for (int q = 0; q < 4; q++) acc[i][n][q] = 0.f;

    int arow  = lane & 15;
    int acol8 = (lane >> 4) * 8;
    int brow  = (lane & 7) + ((lane >> 4) << 3);
    int bcol8 = ((lane >> 3) & 1) * 8;

    auto load_M = [&](int stage, int kt) {
        int kk = kt * 32;
        uint32_t mh = sbase + stage * STAGE_STRIDE + MH_OFF;
        uint32_t ml = sbase + stage * STAGE_STRIDE + ML_OFF;
#pragma unroll
        for (int i = 0; i < 2; i++) {
            int c = tid + 512 * i;
            int n = c >> 2, q = c & 3;
            cp16(mh + n * 80 + q * 16,
                 Mth + (size_t)(bx * 256 + n) * DD + kk + q * 8);
            cp16(ml + n * 80 + q * 16,
                 Mtl + (size_t)(bx * 256 + n) * DD + kk + q * 8);
        }
        asm volatile("cp.async.commit_group;" ::: "memory");
    };

    // x: 128 rows x 32 floats; thread -> row tid>>2, chunk tid&3 (8 floats)
    auto load_x_regs = [&](int kt, float4* vr) {
        int kk = kt * 32;
        int r = tid >> 2, q = tid & 3;
        vr[0] = *(const float4*)(x + (size_t)(by * 128 + r) * DD + kk + q * 8);
        vr[1] = *(const float4*)(x + (size_t)(by * 128 + r) * DD + kk + q * 8 + 4);
    };

    auto store_x = [&](int stage, const float4* vr) {
        uint32_t xh = stage * STAGE_STRIDE + XH_OFF;
        int r = tid >> 2, q = tid & 3;
        float4 v0 = vr[0], v1 = vr[1];
        union { __half2 h[4]; uint4 u; } ph;
        ph.h[0] = __floats2half2_rn(v0.x, v0.y);
        ph.h[1] = __floats2half2_rn(v0.z, v0.w);
        ph.h[2] = __floats2half2_rn(v1.x, v1.y);
        ph.h[3] = __floats2half2_rn(v1.z, v1.w);
        *(uint4*)(smem + xh + r * 80 + q * 16) = ph.u;
    };

    float4 xcur[2];
    load_x_regs(0, xcur);
    load_M(0, 0);
    store_x(0, xcur);

#pragma unroll 1
    for (int kt = 0; kt < NKT; kt++) {
        int cur = kt & 1;
        float4 xnext[2];
        if (kt + 1 < NKT) {
            load_x_regs(kt + 1, xnext);
            load_M(cur ^ 1, kt + 1);
            asm volatile("cp.async.wait_group 1;" ::: "memory");
        } else {
            asm volatile("cp.async.wait_group 0;" ::: "memory");
        }
        __syncthreads();

        uint32_t base = sbase + cur * STAGE_STRIDE;
#pragma unroll
        for (int h = 0; h < 2; h++) {
            uint32_t af[2][4];
#pragma unroll
            for (int i = 0; i < 2; i++) {
                uint32_t rowoff = (uint32_t)(wm * 32 + i * 16 + arow) * 80 +
                                  (uint32_t)(h * 16 + acol8) * 2;
                ldsm4(af[i], base + XH_OFF + rowoff);
            }
#pragma unroll
            for (int jp = 0; jp < 2; jp++) {
                uint32_t bfh[2][4], bfl[2][4];
#pragma unroll
                for (int jj = 0; jj < 2; jj++) {
                    int j = jp * 2 + jj;
                    uint32_t rowoff = (uint32_t)(wn * 64 + j * 16 + brow) * 80 +
                                      (uint32_t)(h * 16 + bcol8) * 2;
                    ldsm4(bfh[jj], base + MH_OFF + rowoff);
                    ldsm4(bfl[jj], base + ML_OFF + rowoff);
                }
#pragma unroll
                for (int i = 0; i < 2; i++)
#pragma unroll
                    for (int jj = 0; jj < 2; jj++) {
                        int n = jp * 4 + 2 * jj;
                        mma16816h(acc[i][n],     af[i], bfh[jj][0], bfh[jj][1]);
                        mma16816h(acc[i][n + 1], af[i], bfh[jj][2], bfh[jj][3]);
                        mma16816h(acc[i][n],     af[i], bfl[jj][0], bfl[jj][1]);
                        mma16816h(acc[i][n + 1], af[i], bfl[jj][2], bfl[jj][3]);
                    }
            }
        }
        if (kt + 1 < NKT) store_x(cur ^ 1, xnext);
        __syncthreads();
    }

    int g = lane >> 2, t4 = lane & 3;
#pragma unroll
    for (int i = 0; i < 2; i++) {
        int r0 = by * 128 + wm * 32 + i * 16 + g;
#pragma unroll
        for (int n = 0; n < 8; n++) {
            int coll = wn * 64 + n * 8 + 2 * t4;
            int colg = bx * 256 + coll;
            float bx0 = sb[coll], bx1 = sb[coll + 1];
            float2 v0 = make_float2(acc[i][n][0] + bx0, acc[i][n][1] + bx1);
            float2 v1 = make_float2(acc[i][n][2] + bx0, acc[i][n][3] + bx1);
            *(float2*)(outf + (size_t)r0 * DD + colg) = v0;
            *(float2*)(outf + (size_t)(r0 + 8) * DD + colg) = v1;
        }
    }
}

// ---------------------------------------------------------------------------
// Attend: one warp per row; 128-thread blocks (5 blocks/SM, 20 warps/SM),
// streaming loads for read-once keys/values. ~163us, at LTS/DRAM ceiling.
// ---------------------------------------------------------------------------
__global__ __launch_bounds__(128) void attend(const float* __restrict__ x,
                                              const float* __restrict__ keys,
                                              const float* __restrict__ values,
                                              float* __restrict__ out) {
    int warp = (blockIdx.x * blockDim.x + threadIdx.x) >> 5;
    int lane = threadIdx.x & 31;
    if (warp >= BSZ) return;

    const float4* xr  = (const float4*)(x + (size_t)warp * DD);
    const float4* q2r = (const float4*)(g_q2 + (size_t)warp * DD);
    const float4* kb  = (const float4*)(keys + (size_t)warp * KN * DD);
    const float4* vb  = (const float4*)(values + (size_t)warp * KN * DD);
    const float4* ur  = (const float4*)g_u;

    float4 xv[4], qv[4];
#pragma unroll
    for (int i = 0; i < 4; i++) {
        xv[i] = xr[lane + 32 * i];
        qv[i] = q2r[lane + 32 * i];
    }

    float qb = 0.f;
#pragma unroll
    for (int i = 0; i < 4; i++) {
        float4 uv = ur[lane + 32 * i];
        qb += xv[i].x * uv.x + xv[i].y * uv.y + xv[i].z * uv.z + xv[i].w * uv.w;
    }
#pragma unroll
    for (int o = 16; o > 0; o >>= 1) qb += __shfl_xor_sync(0xFFFFFFFFu, qb, o);
    qb += g_s0;

    const float scale = 0.044194173824159216f;  // 1/sqrt(512)

    float myscore = 0.f;
    float4 cur[4];
#pragma unroll
    for (int i = 0; i < 4; i++) cur[i] = ldcs4(&kb[lane + 32 * i]);

#pragma unroll
    for (int k = 0; k < KN; k++) {
        float4 nxt[4];
        if (k + 1 < KN) {
#pragma unroll
            for (int i = 0; i < 4; i++)
                nxt[i] = ldcs4(&kb[(k + 1) * 128 + lane + 32 * i]);
        }
        float p = 0.f;
#pragma unroll
        for (int i = 0; i < 4; i++) {
            p += qv[i].x * cur[i].x + qv[i].y * cur[i].y +
                 qv[i].z * cur[i].z + qv[i].w * cur[i].w;
        }
#pragma unroll
        for (int o = 16; o > 0; o >>= 1) p += __shfl_xor_sync(0xFFFFFFFFu, p, o);
        float s = (p + qb) * scale;
        if (lane == k) myscore = s;
#pragma unroll
        for (int i = 0; i < 4; i++) cur[i] = nxt[i];
    }

    float m = myscore;
#pragma unroll
    for (int o = 16; o > 0; o >>= 1)
        m = fmaxf(m, __shfl_xor_sync(0xFFFFFFFFu, m, o));
    float e = expf(myscore - m);
    float sum = e;
#pragma unroll
    for (int o = 16; o > 0; o >>= 1) sum += __shfl_xor_sync(0xFFFFFFFFu, sum, o);
    float a = e / sum;

    float4 acc[4];
#pragma unroll
    for (int i = 0; i < 4; i++) acc[i] = make_float4(0.f, 0.f, 0.f, 0.f);

#pragma unroll
    for (int k = 0; k < KN; k++) {
        float w = __shfl_sync(0xFFFFFFFFu, a, k);
#pragma unroll
        for (int i = 0; i < 4; i++) {
            float4 vv = ldcs4(&vb[k * 128 + lane + 32 * i]);
            acc[i].x += w * vv.x;
            acc[i].y += w * vv.y;
            acc[i].z += w * vv.z;
            acc[i].w += w * vv.w;
        }
    }

    float4* outr = (float4*)(out + (size_t)warp * DD);
#pragma unroll
    for (int i = 0; i < 4; i++) {
        float4 o;
        o.x = 0.5f * xv[i].x + 0.5f * acc[i].x;
        o.y = 0.5f * xv[i].y + 0.5f * acc[i].y;
        o.z = 0.5f * xv[i].z + 0.5f * acc[i].z;
        o.w = 0.5f * xv[i].w + 0.5f * acc[i].w;
        outr[lane + 32 * i] = o;
    }
}

// ---------------------------------------------------------------------------
extern "C" void kernel_launch(void* const* d_in, const int* in_sizes, int n_in,
                              void* d_out, int out_size) {
    const float* x      = (const float*)d_in[0];
    const float* keys   = (const float*)d_in[1];
    const float* values = (const float*)d_in[2];
    const float* w1     = (const float*)d_in[3];
    const float* b1     = (const float*)d_in[4];
    const float* w2     = (const float*)d_in[5];
    const float* b2     = (const float*)d_in[6];
    float* out = (float*)d_out;

    cudaFuncSetAttribute(gemm_fused, cudaFuncAttributeMaxDynamicSharedMemorySize,
                         GSMEM_TOTAL);

    __half *Mth, *Mtl;
    float *q2;
    cudaGetSymbolAddress((void**)&Mth, g_Mth);
    cudaGetSymbolAddress((void**)&Mtl, g_Mtl);
    cudaGetSymbolAddress((void**)&q2, g_q2);

    precompute_all<<<dim3(8, 16), 256>>>(w1, w2, b1, b2);
    gemm_fused<<<dim3(2, 64), 512, GSMEM_TOTAL>>>(x, Mth, Mtl, q2);
    attend<<<(BSZ * 32) / 128, 128>>>(x, keys, values, out);
}

// round 13
// speedup vs baseline: 1.8643x; 1.0807x over previous
#include <cuda_runtime.h>
#include <cuda_bf16.h>
#include <cuda_fp16.h>
#include <math.h>
#include <stdint.h>

#define BSZ 8192
#define KN  32
#define DD  512

// ---------------------------------------------------------------------------
// Device scratch
// ---------------------------------------------------------------------------
__device__ __half g_Mth[DD * DD];          // fp16 of Mt[d][j] = sum_e w1[e][j] w2[e][d]
__device__ float g_q2[BSZ * DD];           // x @ M + c
__device__ float g_c[DD];                  // b1 @ w2
__device__ float g_u[DD];                  // b2 @ w1
__device__ float g_s0;                     // b1 . b2

// ---------------------------------------------------------------------------
// Helpers
// ---------------------------------------------------------------------------
__device__ __forceinline__ uint32_t smem_u32(const void* p) {
    uint32_t a;
    asm("{ .reg .u64 t; cvta.to.shared.u64 t, %1; cvt.u32.u64 %0, t; }"
        : "=r"(a) : "l"(p));
    return a;
}
__device__ __forceinline__ void cp16(uint32_t saddr, const void* g) {
    asm volatile("cp.async.cg.shared.global [%0], [%1], 16;"
                 :: "r"(saddr), "l"(g));
}
__device__ __forceinline__ void ldsm4(uint32_t* r, uint32_t addr) {
    asm volatile("ldmatrix.sync.aligned.m8n8.x4.shared.b16 {%0,%1,%2,%3}, [%4];"
                 : "=r"(r[0]), "=r"(r[1]), "=r"(r[2]), "=r"(r[3]) : "r"(addr));
}
__device__ __forceinline__ void mma16816h(float* c, const uint32_t* a,
                                          uint32_t b0, uint32_t b1) {
    asm volatile(
        "mma.sync.aligned.m16n8k16.row.col.f32.f16.f16.f32 "
        "{%0,%1,%2,%3}, {%4,%5,%6,%7}, {%8,%9}, {%0,%1,%2,%3};"
        : "+f"(c[0]), "+f"(c[1]), "+f"(c[2]), "+f"(c[3])
        : "r"(a[0]), "r"(a[1]), "r"(a[2]), "r"(a[3]), "r"(b0), "r"(b1));
}
__device__ __forceinline__ float4 ldcs4(const float4* p) {
    float4 v;
    asm volatile("ld.global.cs.v4.f32 {%0,%1,%2,%3}, [%4];"
                 : "=f"(v.x), "=f"(v.y), "=f"(v.z), "=f"(v.w) : "l"(p));
    return v;
}

// ---------------------------------------------------------------------------
// precompute_all: cp.async double-buffered register-tiled fp32 GEMM.
//   Mt[d][j] = sum_e w1[e][j] * w2[e][d]  -> fp16 store
// Tile 32(d) x 64(j), grid (8, 16) = 128 blocks, 256 threads, 2x4 per thread.
// Fused borders: u[j] (by==0, tid<64), c[d] (bx==0, tid 64..95), s0 (0,0).
// ---------------------------------------------------------------------------
__global__ __launch_bounds__(256) void precompute_all(
    const float* __restrict__ w1, const float* __restrict__ w2,
    const float* __restrict__ b1, const float* __restrict__ b2) {
    __shared__ float s1[2][32][64];   // w1 [e][j]
    __shared__ float s2[2][32][32];   // w2 [e][d]
    __shared__ float sb1[DD], sb2[DD];
    int tid = threadIdx.x;
    int jg = tid & 15;                // j quad (4 cols)
    int dg = tid >> 4;                // d pair (2 rows)
    int j0 = blockIdx.x * 64, d0 = blockIdx.y * 32;

    sb1[tid] = b1[tid]; sb1[tid + 256] = b1[tid + 256];
    sb2[tid] = b2[tid]; sb2[tid + 256] = b2[tid + 256];

    uint32_t s1b = smem_u32(&s1[0][0][0]);
    uint32_t s2b = smem_u32(&s2[0][0][0]);

    auto load_tile = [&](int st, int e0) {
        {
            int r = tid >> 4, q = tid & 15;
#pragma unroll
            for (int i = 0; i < 2; i++) {
                int rr = r + 16 * i;
                cp16(s1b + (uint32_t)((st * 32 + rr) * 64 + q * 4) * 4,
                     w1 + (size_t)(e0 + rr) * DD + j0 + q * 4);
            }
        }
        {
            int r = tid >> 3, q = tid & 7;
            cp16(s2b + (uint32_t)((st * 32 + r) * 32 + q * 4) * 4,
                 w2 + (size_t)(e0 + r) * DD + d0 + q * 4);
        }
        asm volatile("cp.async.commit_group;" ::: "memory");
    };

    float acc[2][4];
#pragma unroll
    for (int r = 0; r < 2; r++)
#pragma unroll
        for (int c = 0; c < 4; c++) acc[r][c] = 0.f;
    float uacc = 0.f, cacc = 0.f;

    load_tile(0, 0);

#pragma unroll 1
    for (int t = 0; t < 16; t++) {
        int st = t & 1;
        if (t + 1 < 16) {
            load_tile(st ^ 1, (t + 1) * 32);
            asm volatile("cp.async.wait_group 1;" ::: "memory");
        } else {
            asm volatile("cp.async.wait_group 0;" ::: "memory");
        }
        __syncthreads();
#pragma unroll
        for (int e = 0; e < 32; e++) {
            float4 bv = *(const float4*)&s1[st][e][jg * 4];
            float a0 = s2[st][e][dg * 2];
            float a1 = s2[st][e][dg * 2 + 1];
            acc[0][0] += a0 * bv.x; acc[0][1] += a0 * bv.y;
            acc[0][2] += a0 * bv.z; acc[0][3] += a0 * bv.w;
            acc[1][0] += a1 * bv.x; acc[1][1] += a1 * bv.y;
            acc[1][2] += a1 * bv.z; acc[1][3] += a1 * bv.w;
        }
        if (blockIdx.y == 0 && tid < 64) {
            int e0 = t * 32;
#pragma unroll
            for (int e = 0; e < 32; e++) uacc += sb2[e0 + e] * s1[st][e][tid];
        }
        if (blockIdx.x == 0 && tid >= 64 && tid < 96) {
            int e0 = t * 32;
#pragma unroll
            for (int e = 0; e < 32; e++) cacc += sb1[e0 + e] * s2[st][e][tid - 64];
        }
        __syncthreads();
    }

#pragma unroll
    for (int r = 0; r < 2; r++) {
        int d = d0 + dg * 2 + r;
        __half hv[4];
#pragma unroll
        for (int c = 0; c < 4; c++) hv[c] = __float2half(acc[r][c]);
        *(uint2*)&g_Mth[(size_t)d * DD + j0 + jg * 4] = *(uint2*)hv;
    }
    if (blockIdx.y == 0 && tid < 64) g_u[j0 + tid] = uacc;
    if (blockIdx.x == 0 && tid >= 64 && tid < 96) g_c[d0 + tid - 64] = cacc;
    if (blockIdx.x == 0 && blockIdx.y == 0 && tid < 32) {
        float v = 0.f;
#pragma unroll
        for (int q = 0; q < 16; q++) v += sb1[tid + 32 * q] * sb2[tid + 32 * q];
#pragma unroll
        for (int o = 16; o > 0; o >>= 1) v += __shfl_xor_sync(0xFFFFFFFFu, v, o);
        if (tid == 0) g_s0 = v;
    }
}

// ---------------------------------------------------------------------------
// Pure-fp16 GEMM: q2 = fp16(x) @ fp16(M) + c,  K=512 (16 k32 tiles).
// x and M truncation errors are each 2^-11 relative, independent, randomized
// over K=512 -> measured-extrapolated output rel err ~7e-5 (14x margin).
// Block tile 128x256, 512 threads = 16 warps (4m x 4n), warp tile 32x64.
// Grid (2, 64) = 128 blocks, 1 block/SM, 80B-padded smem rows.
// ---------------------------------------------------------------------------
#define NKT 16
#define XH_OFF 0
#define MH_OFF 10240
#define STAGE_STRIDE 30720
#define GSMEM_TOTAL (2 * STAGE_STRIDE + 1024)

__global__ __launch_bounds__(512, 1) void gemm_fused(
    const float* __restrict__ x,
    const __half* __restrict__ Mth,
    float* __restrict__ outf) {
    extern __shared__ char smem[];
    uint32_t sbase = smem_u32(smem);
    int tid = threadIdx.x;
    int lane = tid & 31;
    int warp = tid >> 5;
    int wm = warp >> 2;            // 0..3 (32-row warp tiles)
    int wn = warp & 3;             // 0..3 (64-col warp tiles)
    int bx = blockIdx.x, by = blockIdx.y;

    float* sb = (float*)(smem + 2 * STAGE_STRIDE);
    if (tid < 256) sb[tid] = g_c[bx * 256 + tid];

    float acc[2][8][4];
#pragma unroll
    for (int i = 0; i < 2; i++)
#pragma unroll
        for (int n = 0; n < 8; n++)
#pragma unroll
            for (int q = 0; q < 4; q++) acc[i][n][q] = 0.f;

    int arow  = lane & 15;
    int acol8 = (lane >> 4) * 8;
    int brow  = (lane & 7) + ((lane >> 4) << 3);
    int bcol8 = ((lane >> 3) & 1) * 8;

    auto load_M = [&](int stage, int kt) {
        int kk = kt * 32;
        uint32_t mh = sbase + stage * STAGE_STRIDE + MH_OFF;
#pragma unroll
        for (int i = 0; i < 2; i++) {
            int c = tid + 512 * i;
            int n = c >> 2, q = c & 3;
            cp16(mh + n * 80 + q * 16,
                 Mth + (size_t)(bx * 256 + n) * DD + kk + q * 8);
        }
        asm volatile("cp.async.commit_group;" ::: "memory");
    };

    // x: 128 rows x 32 floats; thread -> row tid>>2, chunk tid&3 (8 floats)
    auto load_x_regs = [&](int kt, float4* vr) {
        int kk = kt * 32;
        int r = tid >> 2, q = tid & 3;
        vr[0] = *(const float4*)(x + (size_t)(by * 128 + r) * DD + kk + q * 8);
        vr[1] = *(const float4*)(x + (size_t)(by * 128 + r) * DD + kk + q * 8 + 4);
    };

    auto store_x = [&](int stage, const float4* vr) {
        uint32_t xh = stage * STAGE_STRIDE + XH_OFF;
        int r = tid >> 2, q = tid & 3;
        float4 v0 = vr[0], v1 = vr[1];
        union { __half2 h[4]; uint4 u; } ph;
        ph.h[0] = __floats2half2_rn(v0.x, v0.y);
        ph.h[1] = __floats2half2_rn(v0.z, v0.w);
        ph.h[2] = __floats2half2_rn(v1.x, v1.y);
        ph.h[3] = __floats2half2_rn(v1.z, v1.w);
        *(uint4*)(smem + xh + r * 80 + q * 16) = ph.u;
    };

    float4 xcur[2];
    load_x_regs(0, xcur);
    load_M(0, 0);
    store_x(0, xcur);

#pragma unroll 1
    for (int kt = 0; kt < NKT; kt++) {
        int cur = kt & 1;
        float4 xnext[2];
        if (kt + 1 < NKT) {
            load_x_regs(kt + 1, xnext);
            load_M(cur ^ 1, kt + 1);
            asm volatile("cp.async.wait_group 1;" ::: "memory");
        } else {
            asm volatile("cp.async.wait_group 0;" ::: "memory");
        }
        __syncthreads();

        uint32_t base = sbase + cur * STAGE_STRIDE;
#pragma unroll
        for (int h = 0; h < 2; h++) {
            uint32_t af[2][4];
#pragma unroll
            for (int i = 0; i < 2; i++) {
                uint32_t rowoff = (uint32_t)(wm * 32 + i * 16 + arow) * 80 +
                                  (uint32_t)(h * 16 + acol8) * 2;
                ldsm4(af[i], base + XH_OFF + rowoff);
            }
#pragma unroll
            for (int jp = 0; jp < 2; jp++) {
                uint32_t bf[2][4];
#pragma unroll
                for (int jj = 0; jj < 2; jj++) {
                    int j = jp * 2 + jj;
                    uint32_t rowoff = (uint32_t)(wn * 64 + j * 16 + brow) * 80 +
                                      (uint32_t)(h * 16 + bcol8) * 2;
                    ldsm4(bf[jj], base + MH_OFF + rowoff);
                }
#pragma unroll
                for (int i = 0; i < 2; i++)
#pragma unroll
                    for (int jj = 0; jj < 2; jj++) {
                        int n = jp * 4 + 2 * jj;
                        mma16816h(acc[i][n],     af[i], bf[jj][0], bf[jj][1]);
                        mma16816h(acc[i][n + 1], af[i], bf[jj][2], bf[jj][3]);
                    }
            }
        }
        if (kt + 1 < NKT) store_x(cur ^ 1, xnext);
        __syncthreads();
    }

    int g = lane >> 2, t4 = lane & 3;
#pragma unroll
    for (int i = 0; i < 2; i++) {
        int r0 = by * 128 + wm * 32 + i * 16 + g;
#pragma unroll
        for (int n = 0; n < 8; n++) {
            int coll = wn * 64 + n * 8 + 2 * t4;
            int colg = bx * 256 + coll;
            float bx0 = sb[coll], bx1 = sb[coll + 1];
            float2 v0 = make_float2(acc[i][n][0] + bx0, acc[i][n][1] + bx1);
            float2 v1 = make_float2(acc[i][n][2] + bx0, acc[i][n][3] + bx1);
            *(float2*)(outf + (size_t)r0 * DD + colg) = v0;
            *(float2*)(outf + (size_t)(r0 + 8) * DD + colg) = v1;
        }
    }
}

// ---------------------------------------------------------------------------
// Attend: one warp per row; 128-thread blocks (5 blocks/SM, 20 warps/SM),
// streaming loads for read-once keys/values. ~163us, at LTS/DRAM ceiling.
// ---------------------------------------------------------------------------
__global__ __launch_bounds__(128) void attend(const float* __restrict__ x,
                                              const float* __restrict__ keys,
                                              const float* __restrict__ values,
                                              float* __restrict__ out) {
    int warp = (blockIdx.x * blockDim.x + threadIdx.x) >> 5;
    int lane = threadIdx.x & 31;
    if (warp >= BSZ) return;

    const float4* xr  = (const float4*)(x + (size_t)warp * DD);
    const float4* q2r = (const float4*)(g_q2 + (size_t)warp * DD);
    const float4* kb  = (const float4*)(keys + (size_t)warp * KN * DD);
    const float4* vb  = (const float4*)(values + (size_t)warp * KN * DD);
    const float4* ur  = (const float4*)g_u;

    float4 xv[4], qv[4];
#pragma unroll
    for (int i = 0; i < 4; i++) {
        xv[i] = xr[lane + 32 * i];
        qv[i] = q2r[lane + 32 * i];
    }

    float qb = 0.f;
#pragma unroll
    for (int i = 0; i < 4; i++) {
        float4 uv = ur[lane + 32 * i];
        qb += xv[i].x * uv.x + xv[i].y * uv.y + xv[i].z * uv.z + xv[i].w * uv.w;
    }
#pragma unroll
    for (int o = 16; o > 0; o >>= 1) qb += __shfl_xor_sync(0xFFFFFFFFu, qb, o);
    qb += g_s0;

    const float scale = 0.044194173824159216f;  // 1/sqrt(512)

    float myscore = 0.f;
    float4 cur[4];
#pragma unroll
    for (int i = 0; i < 4; i++) cur[i] = ldcs4(&kb[lane + 32 * i]);

#pragma unroll
    for (int k = 0; k < KN; k++) {
        float4 nxt[4];
        if (k + 1 < KN) {
#pragma unroll
            for (int i = 0; i < 4; i++)
                nxt[i] = ldcs4(&kb[(k + 1) * 128 + lane + 32 * i]);
        }
        float p = 0.f;
#pragma unroll
        for (int i = 0; i < 4; i++) {
            p += qv[i].x * cur[i].x + qv[i].y * cur[i].y +
                 qv[i].z * cur[i].z + qv[i].w * cur[i].w;
        }
#pragma unroll
        for (int o = 16; o > 0; o >>= 1) p += __shfl_xor_sync(0xFFFFFFFFu, p, o);
        float s = (p + qb) * scale;
        if (lane == k) myscore = s;
#pragma unroll
        for (int i = 0; i < 4; i++) cur[i] = nxt[i];
    }

    float m = myscore;
#pragma unroll
    for (int o = 16; o > 0; o >>= 1)
        m = fmaxf(m, __shfl_xor_sync(0xFFFFFFFFu, m, o));
    float e = expf(myscore - m);
    float sum = e;
#pragma unroll
    for (int o = 16; o > 0; o >>= 1) sum += __shfl_xor_sync(0xFFFFFFFFu, sum, o);
    float a = e / sum;

    float4 acc[4];
#pragma unroll
    for (int i = 0; i < 4; i++) acc[i] = make_float4(0.f, 0.f, 0.f, 0.f);

#pragma unroll
    for (int k = 0; k < KN; k++) {
        float w = __shfl_sync(0xFFFFFFFFu, a, k);
#pragma unroll
        for (int i = 0; i < 4; i++) {
            float4 vv = ldcs4(&vb[k * 128 + lane + 32 * i]);
            acc[i].x += w * vv.x;
            acc[i].y += w * vv.y;
            acc[i].z += w * vv.z;
            acc[i].w += w * vv.w;
        }
    }

    float4* outr = (float4*)(out + (size_t)warp * DD);
#pragma unroll
    for (int i = 0; i < 4; i++) {
        float4 o;
        o.x = 0.5f * xv[i].x + 0.5f * acc[i].x;
        o.y = 0.5f * xv[i].y + 0.5f * acc[i].y;
        o.z = 0.5f * xv[i].z + 0.5f * acc[i].z;
        o.w = 0.5f * xv[i].w + 0.5f * acc[i].w;
        outr[lane + 32 * i] = o;
    }
}

// ---------------------------------------------------------------------------
extern "C" void kernel_launch(void* const* d_in, const int* in_sizes, int n_in,
                              void* d_out, int out_size) {
    const float* x      = (const float*)d_in[0];
    const float* keys   = (const float*)d_in[1];
    const float* values = (const float*)d_in[2];
    const float* w1     = (const float*)d_in[3];
    const float* b1     = (const float*)d_in[4];
    const float* w2     = (const float*)d_in[5];
    const float* b2     = (const float*)d_in[6];
    float* out = (float*)d_out;

    cudaFuncSetAttribute(gemm_fused, cudaFuncAttributeMaxDynamicSharedMemorySize,
                         GSMEM_TOTAL);

    __half *Mth;
    float *q2;
    cudaGetSymbolAddress((void**)&Mth, g_Mth);
    cudaGetSymbolAddress((void**)&q2, g_q2);

    precompute_all<<<dim3(8, 16), 256>>>(w1, w2, b1, b2);
    gemm_fused<<<dim3(2, 64), 512, GSMEM_TOTAL>>>(x, Mth, q2);
    attend<<<(BSZ * 32) / 128, 128>>>(x, keys, values, out);
}